// round 11
// baseline (speedup 1.0000x reference)
#include <cuda_runtime.h>
#include <math.h>
#include <stdint.h>

#define BATCH 16
#define NPTS  2048
#define BKT 32
#define ASTRIDE 36      // (36*grp+tig) mod 32 = 4*grp+tig -> all 32 banks distinct
#define BSTRIDE 136
// small kernel (BM=128, BN=128)
#define BM 128
#define BN 128
#define STAGE_FLOATS (128*ASTRIDE + 128*ASTRIDE)     // 9216
#define SMEM_BYTES (3 * STAGE_FLOATS * 4)            // 110592
// big kernel (BM=256, BN=128)
#define BM2 256
#define STAGE_FLOATS2 (256*ASTRIDE + 128*ASTRIDE)    // 13824
#define SMEM_BYTES2 (3 * STAGE_FLOATS2 * 4)          // 165888
#define QSPLIT 8

// ---------------- scratch (device globals) ----------------
__device__ float g_h24 [(size_t)BATCH*24*NPTS];
__device__ float g_w1p [128*24];
__device__ float g_w2r [256*128];
__device__ float g_w3l [512*256];
__device__ float g_w4r [1024*512];
__device__ float g_wqkr[128*512];
__device__ float g_wvr [512*512];
__device__ float g_wtr [512*512];
__device__ float g_vb  [BATCH*512];
__device__ float g_h128[(size_t)BATCH*128*NPTS];
__device__ unsigned int g_gmu  [BATCH*256];
__device__ unsigned int g_omaxu[BATCH*1024];
__device__ float g_hcat[(size_t)BATCH*512*NPTS];
__device__ float g_h   [(size_t)BATCH*512*NPTS];
__device__ float g_qk  [(size_t)BATCH*128*NPTS];
__device__ float g_qkT [(size_t)BATCH*NPTS*128];
__device__ float g_xv  [(size_t)BATCH*512*NPTS];
__device__ float g_attn[(size_t)BATCH*NPTS*NPTS];
__device__ float g_cs  [BATCH*NPTS];
__device__ float g_cspart[(size_t)QSPLIT*BATCH*NPTS];
__device__ float g_hmxr[(size_t)BATCH*512*NPTS];
__device__ float g_dd  [(size_t)BATCH*512*NPTS];
__device__ float g_mu  [512];
__device__ float g_rs  [512];
__device__ float g_h2  [(size_t)BATCH*512*NPTS];

// ---------------- helpers ----------------
__device__ __forceinline__ uint32_t f2tf(float f){
    uint32_t u;
    asm("cvt.rna.tf32.f32 %0, %1;" : "=r"(u) : "f"(f));
    return u;
}
__device__ __forceinline__ float rnd(float f){ return __uint_as_float(f2tf(f)); }

__device__ __forceinline__ unsigned int fenc(float f){
    unsigned int u = __float_as_uint(f);
    return (u >> 31) ? ~u : (u | 0x80000000u);
}
__device__ __forceinline__ float fdec(unsigned int u){
    return __uint_as_float((u >> 31) ? (u ^ 0x80000000u) : ~u);
}

__device__ __forceinline__ void mma_tf32(float c[4], uint32_t a0, uint32_t a1,
                                         uint32_t a2, uint32_t a3,
                                         uint32_t b0, uint32_t b1){
    asm volatile(
        "mma.sync.aligned.m16n8k8.row.col.f32.tf32.tf32.f32 "
        "{%0,%1,%2,%3}, {%4,%5,%6,%7}, {%8,%9}, {%0,%1,%2,%3};"
        : "+f"(c[0]), "+f"(c[1]), "+f"(c[2]), "+f"(c[3])
        : "r"(a0), "r"(a1), "r"(a2), "r"(a3), "r"(b0), "r"(b1));
}

__device__ __forceinline__ void cp16(uint32_t dst, const float* src, int sz){
    asm volatile("cp.async.cg.shared.global [%0], [%1], 16, %2;"
                 :: "r"(dst), "l"(src), "r"(sz));
}
__device__ __forceinline__ void cp_commit(){ asm volatile("cp.async.commit_group;"); }
__device__ __forceinline__ void cp_wait1(){ asm volatile("cp.async.wait_group 1;"); }

// ---------------- small TF32 GEMM (BM=128, R10 core, for M=128 cases) ----------------
template<int CVTB, int RNDC>
__global__ __launch_bounds__(256, 2)
void mm_tc(const float* __restrict__ A, const float* __restrict__ B,
           const float* __restrict__ bias, const float* __restrict__ bias2,
           float* __restrict__ C,
           int M, int N, int K,
           long a_bat, long b_bat, long c_bat, int relu, int bT,
           const float* __restrict__ colscale, const float* __restrict__ dsub,
           unsigned int* __restrict__ amax)
{
    extern __shared__ float sm[];
    const float* Ab = A + (long)blockIdx.z * a_bat;
    const float* Bb = B + (long)blockIdx.z * b_bat;
    float*       Cb = C ? (C + (long)blockIdx.z * c_bat) : nullptr;
    const int bm = blockIdx.y * BM, bn = blockIdx.x * BN;
    const int tid = threadIdx.x;
    const int lane = tid & 31, wid = tid >> 5;
    const int wm = wid >> 2, wn = wid & 3;
    const int grp = lane >> 2, tig = lane & 3;
    const int ntiles = (K + BKT - 1) / BKT;
    const uint32_t sbase = (uint32_t)__cvta_generic_to_shared(sm);

    float acc[4][4][4];
#pragma unroll
    for (int i = 0; i < 4; i++)
#pragma unroll
        for (int j = 0; j < 4; j++)
#pragma unroll
            for (int r = 0; r < 4; r++) acc[i][j][r] = 0.f;

    auto prefetch = [&](int t){
        if (t >= ntiles) return;
        const int buf = t % 3;
        const uint32_t as0 = sbase + (uint32_t)(buf * STAGE_FLOATS) * 4u;
        const uint32_t bs0 = as0 + (uint32_t)(128 * ASTRIDE) * 4u;
        const int k0 = t * BKT;
#pragma unroll
        for (int i = 0; i < 4; i++) {
            int idx = tid + i*256;
            int mm = idx >> 3, kq = (idx & 7) << 2;
            long kg = (long)k0 + kq;
            long rem = ((long)K - kg) * 4;
            int sz = rem >= 16 ? 16 : (rem > 0 ? (int)rem : 0);
            const float* src = (sz > 0) ? (Ab + (long)(bm + mm)*K + kg) : Ab;
            cp16(as0 + (uint32_t)(mm*ASTRIDE + kq)*4u, src, sz);
        }
        if (!bT) {
#pragma unroll
            for (int i = 0; i < 4; i++) {
                int idx = tid + i*256;
                int kk = idx >> 5, nq = (idx & 31) << 2;
                long kg = (long)k0 + kk;
                int sz = (kg < K) ? 16 : 0;
                const float* src = (sz > 0) ? (Bb + kg*(long)N + (bn + nq)) : Bb;
                cp16(bs0 + (uint32_t)(kk*BSTRIDE + nq)*4u, src, sz);
            }
        } else {
#pragma unroll
            for (int i = 0; i < 4; i++) {
                int idx = tid + i*256;
                int nn = idx >> 3, kq = (idx & 7) << 2;
                long kg = (long)k0 + kq;
                long rem = ((long)K - kg) * 4;
                int sz = rem >= 16 ? 16 : (rem > 0 ? (int)rem : 0);
                const float* src = (sz > 0) ? (Bb + (long)(bn + nn)*K + kg) : Bb;
                cp16(bs0 + (uint32_t)(nn*ASTRIDE + kq)*4u, src, sz);
            }
        }
    };

    prefetch(0); cp_commit();
    prefetch(1); cp_commit();

    for (int t = 0; t < ntiles; t++) {
        cp_wait1();
        __syncthreads();
        const float* As = sm + (t % 3) * STAGE_FLOATS;
        const float* Bs = As + 128 * ASTRIDE;
        const uint32_t* Asu = (const uint32_t*)As;
        const uint32_t* Bsu = (const uint32_t*)Bs;

#pragma unroll
        for (int ks = 0; ks < 4; ks++) {
            const int kb = ks * 8;
            uint32_t af[4][4], bf[4][2];
#pragma unroll
            for (int i = 0; i < 4; i++) {
                int m0 = wm*64 + i*16 + grp;
                const uint32_t* r0 = Asu + m0*ASTRIDE;
                const uint32_t* r1 = r0 + 8*ASTRIDE;
                af[i][0] = r0[kb+tig];
                af[i][1] = r1[kb+tig];
                af[i][2] = r0[kb+tig+4];
                af[i][3] = r1[kb+tig+4];
            }
            if (!bT) {
#pragma unroll
                for (int j = 0; j < 4; j++) {
                    int n0 = wn*32 + j*8 + grp;
                    uint32_t v0 = Bsu[(kb+tig)*BSTRIDE + n0];
                    uint32_t v1 = Bsu[(kb+tig+4)*BSTRIDE + n0];
                    bf[j][0] = CVTB ? f2tf(__uint_as_float(v0)) : v0;
                    bf[j][1] = CVTB ? f2tf(__uint_as_float(v1)) : v1;
                }
            } else {
#pragma unroll
                for (int j = 0; j < 4; j++) {
                    int n0 = wn*32 + j*8 + grp;
                    uint32_t v0 = Bsu[n0*ASTRIDE + kb+tig];
                    uint32_t v1 = Bsu[n0*ASTRIDE + kb+tig+4];
                    bf[j][0] = CVTB ? f2tf(__uint_as_float(v0)) : v0;
                    bf[j][1] = CVTB ? f2tf(__uint_as_float(v1)) : v1;
                }
            }
#pragma unroll
            for (int i = 0; i < 4; i++)
#pragma unroll
                for (int j = 0; j < 4; j++)
                    mma_tf32(acc[i][j], af[i][0], af[i][1], af[i][2], af[i][3],
                             bf[j][0], bf[j][1]);
        }
        prefetch(t + 2); cp_commit();
    }

    const float* csb = colscale ? (colscale + (long)blockIdx.z * N) : nullptr;
    const float* db  = dsub ? (dsub + (long)blockIdx.z * c_bat) : nullptr;

#pragma unroll
    for (int i = 0; i < 4; i++) {
        int mg = bm + wm*64 + i*16 + grp;
        float bi0 = bias ? bias[mg]   : 0.f;
        float bi1 = bias ? bias[mg+8] : 0.f;
        if (bias2) {
            bi0 += bias2[(long)blockIdx.z*M + mg];
            bi1 += bias2[(long)blockIdx.z*M + mg+8];
        }
        float rm0 = -3.402823466e38f, rm1 = -3.402823466e38f;
#pragma unroll
        for (int j = 0; j < 4; j++) {
            int ng = bn + wn*32 + j*8 + tig*2;
            float2 v0, v1;
            v0.x = acc[i][j][0] + bi0; v0.y = acc[i][j][1] + bi0;
            v1.x = acc[i][j][2] + bi1; v1.y = acc[i][j][3] + bi1;
            if (relu) {
                v0.x = fmaxf(v0.x, 0.f); v0.y = fmaxf(v0.y, 0.f);
                v1.x = fmaxf(v1.x, 0.f); v1.y = fmaxf(v1.y, 0.f);
            }
            if (csb) {
                float2 c2 = *(const float2*)(csb + ng);
                float s0 = 1.f / (1e-9f + c2.x), s1 = 1.f / (1e-9f + c2.y);
                v0.x *= s0; v0.y *= s1; v1.x *= s0; v1.y *= s1;
            }
            if (db) {
                float2 d0 = *(const float2*)&db[(long)mg*N + ng];
                float2 d1 = *(const float2*)&db[(long)(mg+8)*N + ng];
                v0.x = d0.x - v0.x; v0.y = d0.y - v0.y;
                v1.x = d1.x - v1.x; v1.y = d1.y - v1.y;
            }
            if (RNDC) {
                v0.x = rnd(v0.x); v0.y = rnd(v0.y);
                v1.x = rnd(v1.x); v1.y = rnd(v1.y);
            }
            if (amax) {
                rm0 = fmaxf(rm0, fmaxf(v0.x, v0.y));
                rm1 = fmaxf(rm1, fmaxf(v1.x, v1.y));
            }
            if (Cb) {
                *(float2*)&Cb[(long)mg*N + ng]     = v0;
                *(float2*)&Cb[(long)(mg+8)*N + ng] = v1;
            }
        }
        if (amax) {
            rm0 = fmaxf(rm0, __shfl_xor_sync(0xffffffffu, rm0, 1));
            rm0 = fmaxf(rm0, __shfl_xor_sync(0xffffffffu, rm0, 2));
            rm1 = fmaxf(rm1, __shfl_xor_sync(0xffffffffu, rm1, 1));
            rm1 = fmaxf(rm1, __shfl_xor_sync(0xffffffffu, rm1, 2));
            if (tig == 0) {
                unsigned int* ab = amax + (long)blockIdx.z * M;
                atomicMax(&ab[mg],   fenc(rm0));
                atomicMax(&ab[mg+8], fenc(rm1));
            }
        }
    }
}

// ---------------- BIG TF32 GEMM: BM=256, BN=128, warp tile 64x64 ----------------
template<int CVTB, int RNDC>
__global__ __launch_bounds__(256, 1)
void mm_tc_big(const float* __restrict__ A, const float* __restrict__ B,
               const float* __restrict__ bias, const float* __restrict__ bias2,
               float* __restrict__ C,
               int M, int N, int K,
               long a_bat, long b_bat, long c_bat, int relu, int bT,
               const float* __restrict__ colscale, const float* __restrict__ dsub,
               unsigned int* __restrict__ amax)
{
    extern __shared__ float sm[];
    const float* Ab = A + (long)blockIdx.z * a_bat;
    const float* Bb = B + (long)blockIdx.z * b_bat;
    float*       Cb = C ? (C + (long)blockIdx.z * c_bat) : nullptr;
    const int bm = blockIdx.y * BM2, bn = blockIdx.x * BN;
    const int tid = threadIdx.x;
    const int lane = tid & 31, wid = tid >> 5;
    const int wm = wid >> 1, wn = wid & 1;      // warp tile (wm*64, wn*64)
    const int grp = lane >> 2, tig = lane & 3;
    const int ntiles = (K + BKT - 1) / BKT;
    const uint32_t sbase = (uint32_t)__cvta_generic_to_shared(sm);

    float acc[4][8][4];
#pragma unroll
    for (int i = 0; i < 4; i++)
#pragma unroll
        for (int j = 0; j < 8; j++)
#pragma unroll
            for (int r = 0; r < 4; r++) acc[i][j][r] = 0.f;

    auto prefetch = [&](int t){
        if (t >= ntiles) return;
        const int buf = t % 3;
        const uint32_t as0 = sbase + (uint32_t)(buf * STAGE_FLOATS2) * 4u;
        const uint32_t bs0 = as0 + (uint32_t)(256 * ASTRIDE) * 4u;
        const int k0 = t * BKT;
        // A tile: 256 rows x 32 k -> 2048 chunks
#pragma unroll
        for (int i = 0; i < 8; i++) {
            int idx = tid + i*256;
            int mm = idx >> 3, kq = (idx & 7) << 2;
            long kg = (long)k0 + kq;
            long rem = ((long)K - kg) * 4;
            int sz = rem >= 16 ? 16 : (rem > 0 ? (int)rem : 0);
            const float* src = (sz > 0) ? (Ab + (long)(bm + mm)*K + kg) : Ab;
            cp16(as0 + (uint32_t)(mm*ASTRIDE + kq)*4u, src, sz);
        }
        if (!bT) {
#pragma unroll
            for (int i = 0; i < 4; i++) {
                int idx = tid + i*256;
                int kk = idx >> 5, nq = (idx & 31) << 2;
                long kg = (long)k0 + kk;
                int sz = (kg < K) ? 16 : 0;
                const float* src = (sz > 0) ? (Bb + kg*(long)N + (bn + nq)) : Bb;
                cp16(bs0 + (uint32_t)(kk*BSTRIDE + nq)*4u, src, sz);
            }
        } else {
#pragma unroll
            for (int i = 0; i < 4; i++) {
                int idx = tid + i*256;
                int nn = idx >> 3, kq = (idx & 7) << 2;
                long kg = (long)k0 + kq;
                long rem = ((long)K - kg) * 4;
                int sz = rem >= 16 ? 16 : (rem > 0 ? (int)rem : 0);
                const float* src = (sz > 0) ? (Bb + (long)(bn + nn)*K + kg) : Bb;
                cp16(bs0 + (uint32_t)(nn*ASTRIDE + kq)*4u, src, sz);
            }
        }
    };

    prefetch(0); cp_commit();
    prefetch(1); cp_commit();

    for (int t = 0; t < ntiles; t++) {
        cp_wait1();
        __syncthreads();
        const float* As = sm + (t % 3) * STAGE_FLOATS2;
        const float* Bs = As + 256 * ASTRIDE;
        const uint32_t* Asu = (const uint32_t*)As;
        const uint32_t* Bsu = (const uint32_t*)Bs;

#pragma unroll
        for (int ks = 0; ks < 4; ks++) {
            const int kb = ks * 8;
            uint32_t af[4][4], bf[8][2];
#pragma unroll
            for (int i = 0; i < 4; i++) {
                int m0 = wm*64 + i*16 + grp;
                const uint32_t* r0 = Asu + m0*ASTRIDE;
                const uint32_t* r1 = r0 + 8*ASTRIDE;
                af[i][0] = r0[kb+tig];
                af[i][1] = r1[kb+tig];
                af[i][2] = r0[kb+tig+4];
                af[i][3] = r1[kb+tig+4];
            }
            if (!bT) {
#pragma unroll
                for (int j = 0; j < 8; j++) {
                    int n0 = wn*64 + j*8 + grp;
                    uint32_t v0 = Bsu[(kb+tig)*BSTRIDE + n0];
                    uint32_t v1 = Bsu[(kb+tig+4)*BSTRIDE + n0];
                    bf[j][0] = CVTB ? f2tf(__uint_as_float(v0)) : v0;
                    bf[j][1] = CVTB ? f2tf(__uint_as_float(v1)) : v1;
                }
            } else {
#pragma unroll
                for (int j = 0; j < 8; j++) {
                    int n0 = wn*64 + j*8 + grp;
                    uint32_t v0 = Bsu[n0*ASTRIDE + kb+tig];
                    uint32_t v1 = Bsu[n0*ASTRIDE + kb+tig+4];
                    bf[j][0] = CVTB ? f2tf(__uint_as_float(v0)) : v0;
                    bf[j][1] = CVTB ? f2tf(__uint_as_float(v1)) : v1;
                }
            }
#pragma unroll
            for (int i = 0; i < 4; i++)
#pragma unroll
                for (int j = 0; j < 8; j++)
                    mma_tf32(acc[i][j], af[i][0], af[i][1], af[i][2], af[i][3],
                             bf[j][0], bf[j][1]);
        }
        prefetch(t + 2); cp_commit();
    }

    const float* csb = colscale ? (colscale + (long)blockIdx.z * N) : nullptr;
    const float* db  = dsub ? (dsub + (long)blockIdx.z * c_bat) : nullptr;

#pragma unroll
    for (int i = 0; i < 4; i++) {
        int mg = bm + wm*64 + i*16 + grp;
        float bi0 = bias ? bias[mg]   : 0.f;
        float bi1 = bias ? bias[mg+8] : 0.f;
        if (bias2) {
            bi0 += bias2[(long)blockIdx.z*M + mg];
            bi1 += bias2[(long)blockIdx.z*M + mg+8];
        }
        float rm0 = -3.402823466e38f, rm1 = -3.402823466e38f;
#pragma unroll
        for (int j = 0; j < 8; j++) {
            int ng = bn + wn*64 + j*8 + tig*2;
            float2 v0, v1;
            v0.x = acc[i][j][0] + bi0; v0.y = acc[i][j][1] + bi0;
            v1.x = acc[i][j][2] + bi1; v1.y = acc[i][j][3] + bi1;
            if (relu) {
                v0.x = fmaxf(v0.x, 0.f); v0.y = fmaxf(v0.y, 0.f);
                v1.x = fmaxf(v1.x, 0.f); v1.y = fmaxf(v1.y, 0.f);
            }
            if (csb) {
                float2 c2 = *(const float2*)(csb + ng);
                float s0 = 1.f / (1e-9f + c2.x), s1 = 1.f / (1e-9f + c2.y);
                v0.x *= s0; v0.y *= s1; v1.x *= s0; v1.y *= s1;
            }
            if (db) {
                float2 d0 = *(const float2*)&db[(long)mg*N + ng];
                float2 d1 = *(const float2*)&db[(long)(mg+8)*N + ng];
                v0.x = d0.x - v0.x; v0.y = d0.y - v0.y;
                v1.x = d1.x - v1.x; v1.y = d1.y - v1.y;
            }
            if (RNDC) {
                v0.x = rnd(v0.x); v0.y = rnd(v0.y);
                v1.x = rnd(v1.x); v1.y = rnd(v1.y);
            }
            if (amax) {
                rm0 = fmaxf(rm0, fmaxf(v0.x, v0.y));
                rm1 = fmaxf(rm1, fmaxf(v1.x, v1.y));
            }
            if (Cb) {
                *(float2*)&Cb[(long)mg*N + ng]     = v0;
                *(float2*)&Cb[(long)(mg+8)*N + ng] = v1;
            }
        }
        if (amax) {
            rm0 = fmaxf(rm0, __shfl_xor_sync(0xffffffffu, rm0, 1));
            rm0 = fmaxf(rm0, __shfl_xor_sync(0xffffffffu, rm0, 2));
            rm1 = fmaxf(rm1, __shfl_xor_sync(0xffffffffu, rm1, 1));
            rm1 = fmaxf(rm1, __shfl_xor_sync(0xffffffffu, rm1, 2));
            if (tig == 0) {
                unsigned int* ab = amax + (long)blockIdx.z * M;
                atomicMax(&ab[mg],   fenc(rm0));
                atomicMax(&ab[mg+8], fenc(rm1));
            }
        }
    }
}

// ---------------- init atomic-max scratch ----------------
__global__ void initmax_k(unsigned int* __restrict__ gmu, unsigned int* __restrict__ omaxu)
{
    int i = blockIdx.x*256 + threadIdx.x;
    if (i < BATCH*256) gmu[i] = 0u;
    if (i < BATCH*1024) omaxu[i] = 0u;
}

// ---------------- one-shot tf32 rounding of weights (w3: packed lower half) ----------------
#define N4_W2  8192
#define N4_W3L 32768
#define N4_W4  131072
#define N4_WQK 16384
#define N4_WV  65536
#define N4_WT  65536
#define N4_TOT (N4_W2 + N4_W3L + N4_W4 + N4_WQK + N4_WV + N4_WT)
__global__ void rndall_k(const float4* w2, const float4* w3, const float4* w4,
                         const float4* wqk, const float4* wv, const float4* wt,
                         float4* w2r, float4* w3l, float4* w4r,
                         float4* wqkr, float4* wvr, float4* wtr)
{
    int i = blockIdx.x*256 + threadIdx.x;
    if (i >= N4_TOT) return;
    float4 v; float4* d;
    if (i < N4_W2) { v = w2[i]; d = w2r + i; }
    else if (i < N4_W2 + N4_W3L) {
        int j = i - N4_W2;
        int m = j >> 6, kq = j & 63;
        v = w3[m*128 + kq];
        d = w3l + j;
    }
    else if (i < N4_W2 + N4_W3L + N4_W4) { int j = i - (N4_W2+N4_W3L); v = w4[j]; d = w4r + j; }
    else if (i < N4_W2 + N4_W3L + N4_W4 + N4_WQK) { int j = i - (N4_W2+N4_W3L+N4_W4); v = wqk[j]; d = wqkr + j; }
    else if (i < N4_W2 + N4_W3L + N4_W4 + N4_WQK + N4_WV) { int j = i - (N4_W2+N4_W3L+N4_W4+N4_WQK); v = wv[j]; d = wvr + j; }
    else { int j = i - (N4_W2+N4_W3L+N4_W4+N4_WQK+N4_WV); v = wt[j]; d = wtr + j; }
    v.x = rnd(v.x); v.y = rnd(v.y); v.z = rnd(v.z); v.w = rnd(v.w);
    *d = v;
}

// ---------------- vb[b][m] = sum_c rnd(w3[m][256+c]) * gm[b][c] ----------------
__global__ void vbias_k(const float* __restrict__ w3, const unsigned int* __restrict__ gmu,
                        float* __restrict__ vb)
{
    int warp = threadIdx.x >> 5, lane = threadIdx.x & 31;
    int m = blockIdx.x*8 + warp;
    int b = blockIdx.y;
    const float* wrow = w3 + (long)m*512 + 256;
    float s = 0.f;
#pragma unroll
    for (int j = 0; j < 8; j++) {
        int c = lane + 32*j;
        s += rnd(wrow[c]) * fdec(gmu[b*256 + c]);
    }
#pragma unroll
    for (int o = 16; o > 0; o >>= 1) s += __shfl_xor_sync(0xffffffffu, s, o);
    if (lane == 0) vb[b*512 + m] = s;
}

// ---------------- positional encoding (24 ch, rounded) ----------------
__global__ void posenc_k(const float* __restrict__ x, float* __restrict__ h24)
{
    int idx = blockIdx.x*blockDim.x + threadIdx.x;
    if (idx >= BATCH*3*NPTS) return;
    int n = idx % NPTS; int r = idx / NPTS;
    int dim = r % 3, b = r / 3;
    float t = x[((long)b*3 + dim)*NPTS + n];
    float* o = h24 + (long)b*24*NPTS + n;
    o[(long)(dim     )*NPTS] = rnd(t);
    o[(long)(3  + dim)*NPTS] = rnd(sinf(t));
    o[(long)(6  + dim)*NPTS] = rnd(cosf(t));
    o[(long)(9  + dim)*NPTS] = rnd(sinf(2.f*t));
    o[(long)(12 + dim)*NPTS] = rnd(cosf(2.f*t));
    o[(long)(15 + dim)*NPTS] = rnd(sinf(4.f*t));
    o[(long)(18 + dim)*NPTS] = rnd(cosf(4.f*t));
    o[(long)(21 + dim)*NPTS] = 0.f;
}

// ---------------- pad+round w1 [128,21] -> [128,24] ----------------
__global__ void w1pad_k(const float* __restrict__ w1, float* __restrict__ w1p)
{
    int i = blockIdx.x*256 + threadIdx.x;
    if (i >= 128*24) return;
    int m = i / 24, k = i % 24;
    w1p[i] = (k < 21) ? rnd(w1[m*21 + k]) : 0.f;
}

// ---------------- transpose qk [128,N] -> qkT [N,128] ----------------
__global__ void tqk_k(const float* __restrict__ qk, float* __restrict__ qkT)
{
    __shared__ float s[32][33];
    int b = blockIdx.z;
    int n0 = blockIdx.x*32, c0 = blockIdx.y*32;
    const float* src = qk + (long)b*128*NPTS;
    float*       dst = qkT + (long)b*NPTS*128;
    int x = threadIdx.x, y = threadIdx.y;
#pragma unroll
    for (int i = 0; i < 4; i++)
        s[y+8*i][x] = src[(long)(c0+y+8*i)*NPTS + n0+x];
    __syncthreads();
#pragma unroll
    for (int i = 0; i < 4; i++)
        dst[(long)(n0+y+8*i)*128 + c0+x] = s[x][y+8*i];
}

// ---------------- warp-per-row softmax: 8 rows/block, MLP-16, shfl-only ----------------
__global__ __launch_bounds__(256)
void softmax_k(float* __restrict__ attn)
{
    int warp = threadIdx.x >> 5, lane = threadIdx.x & 31;
    size_t row = (size_t)blockIdx.x*8 + warp;
    float4* p = (float4*)(attn + row * (size_t)NPTS);
    float4 v[16];
#pragma unroll
    for (int i = 0; i < 16; i++) v[i] = p[lane + 32*i];
    float m = -3.402823466e38f;
#pragma unroll
    for (int i = 0; i < 16; i++)
        m = fmaxf(m, fmaxf(fmaxf(v[i].x, v[i].y), fmaxf(v[i].z, v[i].w)));
#pragma unroll
    for (int o = 16; o > 0; o >>= 1) m = fmaxf(m, __shfl_xor_sync(0xffffffffu, m, o));
    float s = 0.f;
#pragma unroll
    for (int i = 0; i < 16; i++) {
        v[i].x = __expf(v[i].x - m); v[i].y = __expf(v[i].y - m);
        v[i].z = __expf(v[i].z - m); v[i].w = __expf(v[i].w - m);
        s += v[i].x + v[i].y + v[i].z + v[i].w;
    }
#pragma unroll
    for (int o = 16; o > 0; o >>= 1) s += __shfl_xor_sync(0xffffffffu, s, o);
    float inv = 1.f / s;
#pragma unroll
    for (int i = 0; i < 16; i++) {
        v[i].x = rnd(v[i].x * inv); v[i].y = rnd(v[i].y * inv);
        v[i].z = rnd(v[i].z * inv); v[i].w = rnd(v[i].w * inv);
        p[lane + 32*i] = v[i];
    }
}

// ---------------- colsum: float4, q-split partials (deterministic) ----------------
__global__ void colsum_k(const float* __restrict__ attn, float* __restrict__ cspart)
{
    int k4 = blockIdx.x*256 + threadIdx.x;
    int qc = blockIdx.y, b = blockIdx.z;
    const float4* p = (const float4*)(attn + (size_t)b*NPTS*NPTS) + k4;
    float4 s = make_float4(0.f, 0.f, 0.f, 0.f);
    int q0 = qc * (NPTS/QSPLIT);
#pragma unroll 8
    for (int q = q0; q < q0 + NPTS/QSPLIT; q++) {
        float4 v = p[(size_t)q * (NPTS/4)];
        s.x += v.x; s.y += v.y; s.z += v.z; s.w += v.w;
    }
    ((float4*)cspart)[((size_t)qc*BATCH + b)*(NPTS/4) + k4] = s;
}

__global__ void csred_k(const float* __restrict__ cspart, float* __restrict__ cs)
{
    int i = blockIdx.x*256 + threadIdx.x;
    if (i >= BATCH*NPTS) return;
    int b = i / NPTS, k = i % NPTS;
    float s = 0.f;
#pragma unroll
    for (int qc = 0; qc < QSPLIT; qc++)
        s += cspart[((size_t)qc*BATCH + b)*NPTS + k];
    cs[i] = s;
}

// ---------------- BN batch stats per channel (float4 loads) ----------------
__global__ void bnstats_k(const float* __restrict__ d)
{
    int c = blockIdx.x;
    int t = threadIdx.x;
    double s = 0.0, s2 = 0.0;
    for (int i4 = t; i4 < BATCH*NPTS/4; i4 += 256) {
        int b = i4 / (NPTS/4), n4 = i4 % (NPTS/4);
        float4 v = ((const float4*)(d + ((long)b*512 + c)*NPTS))[n4];
        s  += (double)v.x + (double)v.y + (double)v.z + (double)v.w;
        s2 += (double)v.x*v.x + (double)v.y*v.y + (double)v.z*v.z + (double)v.w*v.w;
    }
    __shared__ double sh[256], sh2[256];
    sh[t] = s; sh2[t] = s2; __syncthreads();
    for (int o = 128; o > 0; o >>= 1) {
        if (t < o) { sh[t] += sh[t+o]; sh2[t] += sh2[t+o]; }
        __syncthreads();
    }
    if (t == 0) {
        double mu  = sh[0]  / (double)(BATCH*NPTS);
        double var = sh2[0] / (double)(BATCH*NPTS) - mu*mu;
        g_mu[c] = (float)mu;
        g_rs[c] = (float)(1.0 / sqrt(var + 1e-5));
    }
}

// ---------------- h2 = rnd(h + relu(bn(d))) (float4) ----------------
__global__ void bnapply_k(const float* __restrict__ h, const float* __restrict__ d,
                          const float* __restrict__ gamma, const float* __restrict__ beta,
                          float* __restrict__ h2)
{
    long i = (long)blockIdx.x*256 + threadIdx.x;
    if (i >= (long)BATCH*512*NPTS/4) return;
    int c = (int)((i / (NPTS/4)) % 512);
    float ga = gamma[c], mu = g_mu[c], rs = g_rs[c], be = beta[c];
    float4 dv = ((const float4*)d)[i];
    float4 hv = ((const float4*)h)[i];
    float4 r;
    r.x = rnd(hv.x + fmaxf(ga*(dv.x - mu)*rs + be, 0.f));
    r.y = rnd(hv.y + fmaxf(ga*(dv.y - mu)*rs + be, 0.f));
    r.z = rnd(hv.z + fmaxf(ga*(dv.z - mu)*rs + be, 0.f));
    r.w = rnd(hv.w + fmaxf(ga*(dv.w - mu)*rs + be, 0.f));
    ((float4*)h2)[i] = r;
}

// ---------------- decode ordered-uint maxes into fp32 output ----------------
__global__ void decout_k(const unsigned int* __restrict__ omaxu, float* __restrict__ out)
{
    int i = blockIdx.x*256 + threadIdx.x;
    if (i >= BATCH*1024) return;
    out[i] = fdec(omaxu[i]);
}

// ---------------- launch ----------------
extern "C" void kernel_launch(void* const* d_in, const int* in_sizes, int n_in,
                              void* d_out, int out_size)
{
    const float* x    = (const float*)d_in[0];
    const float* w1   = (const float*)d_in[1];
    const float* b1   = (const float*)d_in[2];
    const float* w2   = (const float*)d_in[3];
    const float* b2   = (const float*)d_in[4];
    const float* w3   = (const float*)d_in[5];
    const float* b3   = (const float*)d_in[6];
    const float* w4   = (const float*)d_in[7];
    const float* b4   = (const float*)d_in[8];
    const float* wqk  = (const float*)d_in[9];
    const float* wv   = (const float*)d_in[10];
    const float* bv   = (const float*)d_in[11];
    const float* wt   = (const float*)d_in[12];
    const float* bt   = (const float*)d_in[13];
    const float* gamma= (const float*)d_in[14];
    const float* beta = (const float*)d_in[15];
    float* out = (float*)d_out;

    static bool attr_set = false;
    if (!attr_set) {
        cudaFuncSetAttribute(mm_tc<0,0>, cudaFuncAttributeMaxDynamicSharedMemorySize, SMEM_BYTES);
        cudaFuncSetAttribute(mm_tc<0,1>, cudaFuncAttributeMaxDynamicSharedMemorySize, SMEM_BYTES);
        cudaFuncSetAttribute(mm_tc<1,1>, cudaFuncAttributeMaxDynamicSharedMemorySize, SMEM_BYTES);
        cudaFuncSetAttribute(mm_tc_big<0,0>, cudaFuncAttributeMaxDynamicSharedMemorySize, SMEM_BYTES2);
        cudaFuncSetAttribute(mm_tc_big<0,1>, cudaFuncAttributeMaxDynamicSharedMemorySize, SMEM_BYTES2);
        cudaFuncSetAttribute(mm_tc_big<1,1>, cudaFuncAttributeMaxDynamicSharedMemorySize, SMEM_BYTES2);
        attr_set = true;
    }

    float *h24,*w1p,*w2r,*w3l,*w4r,*wqkr,*wvr,*wtr,*vb;
    float *h128,*hcat,*h,*qk,*qkT,*xv,*attn,*cs,*cspart,*hmxr,*dd,*h2;
    unsigned int *gmu,*omaxu;
    cudaGetSymbolAddress((void**)&h24,  g_h24);
    cudaGetSymbolAddress((void**)&w1p,  g_w1p);
    cudaGetSymbolAddress((void**)&w2r,  g_w2r);
    cudaGetSymbolAddress((void**)&w3l,  g_w3l);
    cudaGetSymbolAddress((void**)&w4r,  g_w4r);
    cudaGetSymbolAddress((void**)&wqkr, g_wqkr);
    cudaGetSymbolAddress((void**)&wvr,  g_wvr);
    cudaGetSymbolAddress((void**)&wtr,  g_wtr);
    cudaGetSymbolAddress((void**)&vb,   g_vb);
    cudaGetSymbolAddress((void**)&h128, g_h128);
    cudaGetSymbolAddress((void**)&gmu,  g_gmu);
    cudaGetSymbolAddress((void**)&omaxu,g_omaxu);
    cudaGetSymbolAddress((void**)&hcat, g_hcat);
    cudaGetSymbolAddress((void**)&h,    g_h);
    cudaGetSymbolAddress((void**)&qk,   g_qk);
    cudaGetSymbolAddress((void**)&qkT,  g_qkT);
    cudaGetSymbolAddress((void**)&xv,   g_xv);
    cudaGetSymbolAddress((void**)&attn, g_attn);
    cudaGetSymbolAddress((void**)&cs,   g_cs);
    cudaGetSymbolAddress((void**)&cspart, g_cspart);
    cudaGetSymbolAddress((void**)&hmxr, g_hmxr);
    cudaGetSymbolAddress((void**)&dd,   g_dd);
    cudaGetSymbolAddress((void**)&h2,   g_h2);

    const long EW = (long)BATCH*512*NPTS;

    initmax_k<<<(BATCH*1024 + 255)/256, 256>>>(gmu, omaxu);
    posenc_k<<<(BATCH*3*NPTS + 255)/256, 256>>>(x, h24);
    w1pad_k<<<(128*24 + 255)/256, 256>>>(w1, w1p);
    rndall_k<<<(N4_TOT + 255)/256, 256>>>(
        (const float4*)w2, (const float4*)w3, (const float4*)w4,
        (const float4*)wqk, (const float4*)wv, (const float4*)wt,
        (float4*)w2r, (float4*)w3l, (float4*)w4r,
        (float4*)wqkr, (float4*)wvr, (float4*)wtr);

    // conv1 (24->128) + relu, rounded out  [small: M=128]
    mm_tc<0,1><<<dim3(16,1,BATCH),256,SMEM_BYTES>>>(w1p, h24, b1, nullptr, h128,
        128, NPTS, 24, 0, (long)24*NPTS, (long)128*NPTS, 1, 0, nullptr, nullptr, nullptr);
    // conv2 (128->256), rounded, hcat lower half + fused global max  [big]
    mm_tc_big<0,1><<<dim3(16,1,BATCH),256,SMEM_BYTES2>>>(w2r, h128, b2, nullptr, hcat,
        256, NPTS, 128, 0, (long)128*NPTS, (long)512*NPTS, 0, 0, nullptr, nullptr, gmu);
    vbias_k<<<dim3(64, BATCH), 256>>>(w3, gmu, vb);
    // conv3 lower half (K=256) + vb + relu -> h  [big]
    mm_tc_big<0,0><<<dim3(16,2,BATCH),256,SMEM_BYTES2>>>(w3l, hcat, b3, vb, h,
        512, NPTS, 256, 0, (long)512*NPTS, (long)512*NPTS, 1, 0, nullptr, nullptr, nullptr);
    // q/k projection  [small: M=128]
    mm_tc<1,1><<<dim3(16,1,BATCH),256,SMEM_BYTES>>>(wqkr, h, nullptr, nullptr, qk,
        128, NPTS, 512, 0, (long)512*NPTS, (long)128*NPTS, 0, 0, nullptr, nullptr, nullptr);
    tqk_k<<<dim3(NPTS/32, 4, BATCH), dim3(32,8)>>>(qk, qkT);
    // energy = qkT @ qk  [big]
    mm_tc_big<0,0><<<dim3(16,8,BATCH),256,SMEM_BYTES2>>>(qkT, qk, nullptr, nullptr, attn,
        NPTS, NPTS, 128, (long)NPTS*128, (long)128*NPTS, (long)NPTS*NPTS, 0, 0,
        nullptr, nullptr, nullptr);
    softmax_k<<<BATCH*NPTS/8, 256>>>(attn);
    colsum_k<<<dim3(NPTS/4/256, QSPLIT, BATCH), 256>>>(attn, cspart);
    csred_k<<<(BATCH*NPTS + 255)/256, 256>>>(cspart, cs);
    // v projection + fused colsum scale  [big]
    mm_tc_big<1,1><<<dim3(16,2,BATCH),256,SMEM_BYTES2>>>(wvr, h, bv, nullptr, xv,
        512, NPTS, 512, 0, (long)512*NPTS, (long)512*NPTS, 0, 0, cs, nullptr, nullptr);
    // hmxr = rnd(h - xv_scaled @ attn^T)  [big, bT]
    mm_tc_big<0,1><<<dim3(16,2,BATCH),256,SMEM_BYTES2>>>(xv, attn, nullptr, nullptr, hmxr,
        512, NPTS, NPTS, (long)512*NPTS, (long)NPTS*NPTS, (long)512*NPTS, 0, 1,
        nullptr, h, nullptr);
    // d = wt @ (h - x_r) + bt  [big]
    mm_tc_big<0,0><<<dim3(16,2,BATCH),256,SMEM_BYTES2>>>(wtr, hmxr, bt, nullptr, dd,
        512, NPTS, 512, 0, (long)512*NPTS, (long)512*NPTS, 0, 0, nullptr, nullptr, nullptr);
    bnstats_k<<<512, 256>>>(dd);
    bnapply_k<<<(int)((EW/4 + 255)/256), 256>>>(h, dd, gamma, beta, h2);
    // conv4 (512->1024) fused with final max  [big]
    mm_tc_big<0,0><<<dim3(16,4,BATCH),256,SMEM_BYTES2>>>(w4r, h2, b4, nullptr, nullptr,
        1024, NPTS, 512, 0, (long)512*NPTS, 0, 0, 0, nullptr, nullptr, omaxu);
    decout_k<<<(BATCH*1024 + 255)/256, 256>>>(omaxu, out);
}

// round 12
// speedup vs baseline: 1.0234x; 1.0234x over previous
#include <cuda_runtime.h>
#include <math.h>
#include <stdint.h>

#define BATCH 16
#define NPTS  2048
#define BKT 32
#define ASTRIDE 36      // (36*grp+tig) mod 32 = 4*grp+tig -> all 32 banks distinct
#define BSTRIDE 136
// small kernel (BM=128, BN=128, 256 thr, 2 CTA/SM)
#define BM 128
#define BN 128
#define STAGE_FLOATS (128*ASTRIDE + 128*ASTRIDE)     // 9216
#define SMEM_BYTES (3 * STAGE_FLOATS * 4)            // 110592
// big kernel (BM=256, BN=128, 512 thr, 1 CTA/SM)
#define BM2 256
#define STAGE_FLOATS2 (256*ASTRIDE + 128*ASTRIDE)    // 13824
#define SMEM_BYTES2 (3 * STAGE_FLOATS2 * 4)          // 165888
#define QSPLIT 8

// ---------------- scratch (device globals) ----------------
__device__ float g_h24 [(size_t)BATCH*24*NPTS];
__device__ float g_w1p [128*24];
__device__ float g_w2r [256*128];
__device__ float g_w3l [512*256];
__device__ float g_w4r [1024*512];
__device__ float g_wqkr[128*512];
__device__ float g_wvr [512*512];
__device__ float g_wtr [512*512];
__device__ float g_vb  [BATCH*512];
__device__ float g_h128[(size_t)BATCH*128*NPTS];
__device__ unsigned int g_gmu  [BATCH*256];
__device__ unsigned int g_omaxu[BATCH*1024];
__device__ float g_hcat[(size_t)BATCH*512*NPTS];
__device__ float g_h   [(size_t)BATCH*512*NPTS];
__device__ float g_qk  [(size_t)BATCH*128*NPTS];
__device__ float g_qkT [(size_t)BATCH*NPTS*128];
__device__ float g_xv  [(size_t)BATCH*512*NPTS];
__device__ float g_attn[(size_t)BATCH*NPTS*NPTS];
__device__ float g_cs  [BATCH*NPTS];
__device__ float g_cspart[(size_t)QSPLIT*BATCH*NPTS];
__device__ float g_hmxr[(size_t)BATCH*512*NPTS];
__device__ float g_dd  [(size_t)BATCH*512*NPTS];
__device__ float g_mu  [512];
__device__ float g_rs  [512];
__device__ float g_h2  [(size_t)BATCH*512*NPTS];

// ---------------- helpers ----------------
__device__ __forceinline__ uint32_t f2tf(float f){
    uint32_t u;
    asm("cvt.rna.tf32.f32 %0, %1;" : "=r"(u) : "f"(f));
    return u;
}
__device__ __forceinline__ float rnd(float f){ return __uint_as_float(f2tf(f)); }

__device__ __forceinline__ unsigned int fenc(float f){
    unsigned int u = __float_as_uint(f);
    return (u >> 31) ? ~u : (u | 0x80000000u);
}
__device__ __forceinline__ float fdec(unsigned int u){
    return __uint_as_float((u >> 31) ? (u ^ 0x80000000u) : ~u);
}

__device__ __forceinline__ void mma_tf32(float c[4], uint32_t a0, uint32_t a1,
                                         uint32_t a2, uint32_t a3,
                                         uint32_t b0, uint32_t b1){
    asm volatile(
        "mma.sync.aligned.m16n8k8.row.col.f32.tf32.tf32.f32 "
        "{%0,%1,%2,%3}, {%4,%5,%6,%7}, {%8,%9}, {%0,%1,%2,%3};"
        : "+f"(c[0]), "+f"(c[1]), "+f"(c[2]), "+f"(c[3])
        : "r"(a0), "r"(a1), "r"(a2), "r"(a3), "r"(b0), "r"(b1));
}

__device__ __forceinline__ void cp16(uint32_t dst, const float* src, int sz){
    asm volatile("cp.async.cg.shared.global [%0], [%1], 16, %2;"
                 :: "r"(dst), "l"(src), "r"(sz));
}
__device__ __forceinline__ void cp_commit(){ asm volatile("cp.async.commit_group;"); }
__device__ __forceinline__ void cp_wait1(){ asm volatile("cp.async.wait_group 1;"); }

// ---------------- small TF32 GEMM (BM=128, R10 core, for M=128 cases) ----------------
template<int CVTB, int RNDC>
__global__ __launch_bounds__(256, 2)
void mm_tc(const float* __restrict__ A, const float* __restrict__ B,
           const float* __restrict__ bias, const float* __restrict__ bias2,
           float* __restrict__ C,
           int M, int N, int K,
           long a_bat, long b_bat, long c_bat, int relu, int bT,
           const float* __restrict__ colscale, const float* __restrict__ dsub,
           unsigned int* __restrict__ amax)
{
    extern __shared__ float sm[];
    const float* Ab = A + (long)blockIdx.z * a_bat;
    const float* Bb = B + (long)blockIdx.z * b_bat;
    float*       Cb = C ? (C + (long)blockIdx.z * c_bat) : nullptr;
    const int bm = blockIdx.y * BM, bn = blockIdx.x * BN;
    const int tid = threadIdx.x;
    const int lane = tid & 31, wid = tid >> 5;
    const int wm = wid >> 2, wn = wid & 3;
    const int grp = lane >> 2, tig = lane & 3;
    const int ntiles = (K + BKT - 1) / BKT;
    const uint32_t sbase = (uint32_t)__cvta_generic_to_shared(sm);

    float acc[4][4][4];
#pragma unroll
    for (int i = 0; i < 4; i++)
#pragma unroll
        for (int j = 0; j < 4; j++)
#pragma unroll
            for (int r = 0; r < 4; r++) acc[i][j][r] = 0.f;

    auto prefetch = [&](int t){
        if (t >= ntiles) return;
        const int buf = t % 3;
        const uint32_t as0 = sbase + (uint32_t)(buf * STAGE_FLOATS) * 4u;
        const uint32_t bs0 = as0 + (uint32_t)(128 * ASTRIDE) * 4u;
        const int k0 = t * BKT;
#pragma unroll
        for (int i = 0; i < 4; i++) {
            int idx = tid + i*256;
            int mm = idx >> 3, kq = (idx & 7) << 2;
            long kg = (long)k0 + kq;
            long rem = ((long)K - kg) * 4;
            int sz = rem >= 16 ? 16 : (rem > 0 ? (int)rem : 0);
            const float* src = (sz > 0) ? (Ab + (long)(bm + mm)*K + kg) : Ab;
            cp16(as0 + (uint32_t)(mm*ASTRIDE + kq)*4u, src, sz);
        }
        if (!bT) {
#pragma unroll
            for (int i = 0; i < 4; i++) {
                int idx = tid + i*256;
                int kk = idx >> 5, nq = (idx & 31) << 2;
                long kg = (long)k0 + kk;
                int sz = (kg < K) ? 16 : 0;
                const float* src = (sz > 0) ? (Bb + kg*(long)N + (bn + nq)) : Bb;
                cp16(bs0 + (uint32_t)(kk*BSTRIDE + nq)*4u, src, sz);
            }
        } else {
#pragma unroll
            for (int i = 0; i < 4; i++) {
                int idx = tid + i*256;
                int nn = idx >> 3, kq = (idx & 7) << 2;
                long kg = (long)k0 + kq;
                long rem = ((long)K - kg) * 4;
                int sz = rem >= 16 ? 16 : (rem > 0 ? (int)rem : 0);
                const float* src = (sz > 0) ? (Bb + (long)(bn + nn)*K + kg) : Bb;
                cp16(bs0 + (uint32_t)(nn*ASTRIDE + kq)*4u, src, sz);
            }
        }
    };

    prefetch(0); cp_commit();
    prefetch(1); cp_commit();

    for (int t = 0; t < ntiles; t++) {
        cp_wait1();
        __syncthreads();
        const float* As = sm + (t % 3) * STAGE_FLOATS;
        const float* Bs = As + 128 * ASTRIDE;
        const uint32_t* Asu = (const uint32_t*)As;
        const uint32_t* Bsu = (const uint32_t*)Bs;

#pragma unroll
        for (int ks = 0; ks < 4; ks++) {
            const int kb = ks * 8;
            uint32_t af[4][4], bf[4][2];
#pragma unroll
            for (int i = 0; i < 4; i++) {
                int m0 = wm*64 + i*16 + grp;
                const uint32_t* r0 = Asu + m0*ASTRIDE;
                const uint32_t* r1 = r0 + 8*ASTRIDE;
                af[i][0] = r0[kb+tig];
                af[i][1] = r1[kb+tig];
                af[i][2] = r0[kb+tig+4];
                af[i][3] = r1[kb+tig+4];
            }
            if (!bT) {
#pragma unroll
                for (int j = 0; j < 4; j++) {
                    int n0 = wn*32 + j*8 + grp;
                    uint32_t v0 = Bsu[(kb+tig)*BSTRIDE + n0];
                    uint32_t v1 = Bsu[(kb+tig+4)*BSTRIDE + n0];
                    bf[j][0] = CVTB ? f2tf(__uint_as_float(v0)) : v0;
                    bf[j][1] = CVTB ? f2tf(__uint_as_float(v1)) : v1;
                }
            } else {
#pragma unroll
                for (int j = 0; j < 4; j++) {
                    int n0 = wn*32 + j*8 + grp;
                    uint32_t v0 = Bsu[n0*ASTRIDE + kb+tig];
                    uint32_t v1 = Bsu[n0*ASTRIDE + kb+tig+4];
                    bf[j][0] = CVTB ? f2tf(__uint_as_float(v0)) : v0;
                    bf[j][1] = CVTB ? f2tf(__uint_as_float(v1)) : v1;
                }
            }
#pragma unroll
            for (int i = 0; i < 4; i++)
#pragma unroll
                for (int j = 0; j < 4; j++)
                    mma_tf32(acc[i][j], af[i][0], af[i][1], af[i][2], af[i][3],
                             bf[j][0], bf[j][1]);
        }
        prefetch(t + 2); cp_commit();
    }

    const float* csb = colscale ? (colscale + (long)blockIdx.z * N) : nullptr;
    const float* db  = dsub ? (dsub + (long)blockIdx.z * c_bat) : nullptr;

#pragma unroll
    for (int i = 0; i < 4; i++) {
        int mg = bm + wm*64 + i*16 + grp;
        float bi0 = bias ? bias[mg]   : 0.f;
        float bi1 = bias ? bias[mg+8] : 0.f;
        if (bias2) {
            bi0 += bias2[(long)blockIdx.z*M + mg];
            bi1 += bias2[(long)blockIdx.z*M + mg+8];
        }
        float rm0 = -3.402823466e38f, rm1 = -3.402823466e38f;
#pragma unroll
        for (int j = 0; j < 4; j++) {
            int ng = bn + wn*32 + j*8 + tig*2;
            float2 v0, v1;
            v0.x = acc[i][j][0] + bi0; v0.y = acc[i][j][1] + bi0;
            v1.x = acc[i][j][2] + bi1; v1.y = acc[i][j][3] + bi1;
            if (relu) {
                v0.x = fmaxf(v0.x, 0.f); v0.y = fmaxf(v0.y, 0.f);
                v1.x = fmaxf(v1.x, 0.f); v1.y = fmaxf(v1.y, 0.f);
            }
            if (csb) {
                float2 c2 = *(const float2*)(csb + ng);
                float s0 = 1.f / (1e-9f + c2.x), s1 = 1.f / (1e-9f + c2.y);
                v0.x *= s0; v0.y *= s1; v1.x *= s0; v1.y *= s1;
            }
            if (db) {
                float2 d0 = *(const float2*)&db[(long)mg*N + ng];
                float2 d1 = *(const float2*)&db[(long)(mg+8)*N + ng];
                v0.x = d0.x - v0.x; v0.y = d0.y - v0.y;
                v1.x = d1.x - v1.x; v1.y = d1.y - v1.y;
            }
            if (RNDC) {
                v0.x = rnd(v0.x); v0.y = rnd(v0.y);
                v1.x = rnd(v1.x); v1.y = rnd(v1.y);
            }
            if (amax) {
                rm0 = fmaxf(rm0, fmaxf(v0.x, v0.y));
                rm1 = fmaxf(rm1, fmaxf(v1.x, v1.y));
            }
            if (Cb) {
                *(float2*)&Cb[(long)mg*N + ng]     = v0;
                *(float2*)&Cb[(long)(mg+8)*N + ng] = v1;
            }
        }
        if (amax) {
            rm0 = fmaxf(rm0, __shfl_xor_sync(0xffffffffu, rm0, 1));
            rm0 = fmaxf(rm0, __shfl_xor_sync(0xffffffffu, rm0, 2));
            rm1 = fmaxf(rm1, __shfl_xor_sync(0xffffffffu, rm1, 1));
            rm1 = fmaxf(rm1, __shfl_xor_sync(0xffffffffu, rm1, 2));
            if (tig == 0) {
                unsigned int* ab = amax + (long)blockIdx.z * M;
                atomicMax(&ab[mg],   fenc(rm0));
                atomicMax(&ab[mg+8], fenc(rm1));
            }
        }
    }
}

// ---------------- BIG TF32 GEMM: BM=256, BN=128, 512 threads, warp tile 64x32 ----------------
template<int CVTB, int RNDC>
__global__ __launch_bounds__(512, 1)
void mm_tc_big(const float* __restrict__ A, const float* __restrict__ B,
               const float* __restrict__ bias, const float* __restrict__ bias2,
               float* __restrict__ C,
               int M, int N, int K,
               long a_bat, long b_bat, long c_bat, int relu, int bT,
               const float* __restrict__ colscale, const float* __restrict__ dsub,
               unsigned int* __restrict__ amax)
{
    extern __shared__ float sm[];
    const float* Ab = A + (long)blockIdx.z * a_bat;
    const float* Bb = B + (long)blockIdx.z * b_bat;
    float*       Cb = C ? (C + (long)blockIdx.z * c_bat) : nullptr;
    const int bm = blockIdx.y * BM2, bn = blockIdx.x * BN;
    const int tid = threadIdx.x;
    const int lane = tid & 31, wid = tid >> 5;       // 16 warps
    const int wm = wid >> 2, wn = wid & 3;           // 4x4 warp grid, tile 64x32
    const int grp = lane >> 2, tig = lane & 3;
    const int ntiles = (K + BKT - 1) / BKT;
    const uint32_t sbase = (uint32_t)__cvta_generic_to_shared(sm);

    float acc[4][4][4];
#pragma unroll
    for (int i = 0; i < 4; i++)
#pragma unroll
        for (int j = 0; j < 4; j++)
#pragma unroll
            for (int r = 0; r < 4; r++) acc[i][j][r] = 0.f;

    auto prefetch = [&](int t){
        if (t >= ntiles) return;
        const int buf = t % 3;
        const uint32_t as0 = sbase + (uint32_t)(buf * STAGE_FLOATS2) * 4u;
        const uint32_t bs0 = as0 + (uint32_t)(256 * ASTRIDE) * 4u;
        const int k0 = t * BKT;
        // A tile: 256 rows x 32 k -> 2048 chunks / 512 thr = 4 iters
#pragma unroll
        for (int i = 0; i < 4; i++) {
            int idx = tid + i*512;
            int mm = idx >> 3, kq = (idx & 7) << 2;
            long kg = (long)k0 + kq;
            long rem = ((long)K - kg) * 4;
            int sz = rem >= 16 ? 16 : (rem > 0 ? (int)rem : 0);
            const float* src = (sz > 0) ? (Ab + (long)(bm + mm)*K + kg) : Ab;
            cp16(as0 + (uint32_t)(mm*ASTRIDE + kq)*4u, src, sz);
        }
        if (!bT) {
            // B tile: 32 k-rows x 128 n -> 1024 chunks / 512 thr = 2 iters
#pragma unroll
            for (int i = 0; i < 2; i++) {
                int idx = tid + i*512;
                int kk = idx >> 5, nq = (idx & 31) << 2;
                long kg = (long)k0 + kk;
                int sz = (kg < K) ? 16 : 0;
                const float* src = (sz > 0) ? (Bb + kg*(long)N + (bn + nq)) : Bb;
                cp16(bs0 + (uint32_t)(kk*BSTRIDE + nq)*4u, src, sz);
            }
        } else {
            // B tile: 128 n-rows x 32 k -> 1024 chunks / 512 thr = 2 iters
#pragma unroll
            for (int i = 0; i < 2; i++) {
                int idx = tid + i*512;
                int nn = idx >> 3, kq = (idx & 7) << 2;
                long kg = (long)k0 + kq;
                long rem = ((long)K - kg) * 4;
                int sz = rem >= 16 ? 16 : (rem > 0 ? (int)rem : 0);
                const float* src = (sz > 0) ? (Bb + (long)(bn + nn)*K + kg) : Bb;
                cp16(bs0 + (uint32_t)(nn*ASTRIDE + kq)*4u, src, sz);
            }
        }
    };

    prefetch(0); cp_commit();
    prefetch(1); cp_commit();

    for (int t = 0; t < ntiles; t++) {
        cp_wait1();
        __syncthreads();
        const float* As = sm + (t % 3) * STAGE_FLOATS2;
        const float* Bs = As + 256 * ASTRIDE;
        const uint32_t* Asu = (const uint32_t*)As;
        const uint32_t* Bsu = (const uint32_t*)Bs;

#pragma unroll
        for (int ks = 0; ks < 4; ks++) {
            const int kb = ks * 8;
            uint32_t af[4][4], bf[4][2];
#pragma unroll
            for (int i = 0; i < 4; i++) {
                int m0 = wm*64 + i*16 + grp;
                const uint32_t* r0 = Asu + m0*ASTRIDE;
                const uint32_t* r1 = r0 + 8*ASTRIDE;
                af[i][0] = r0[kb+tig];
                af[i][1] = r1[kb+tig];
                af[i][2] = r0[kb+tig+4];
                af[i][3] = r1[kb+tig+4];
            }
            if (!bT) {
#pragma unroll
                for (int j = 0; j < 4; j++) {
                    int n0 = wn*32 + j*8 + grp;
                    uint32_t v0 = Bsu[(kb+tig)*BSTRIDE + n0];
                    uint32_t v1 = Bsu[(kb+tig+4)*BSTRIDE + n0];
                    bf[j][0] = CVTB ? f2tf(__uint_as_float(v0)) : v0;
                    bf[j][1] = CVTB ? f2tf(__uint_as_float(v1)) : v1;
                }
            } else {
#pragma unroll
                for (int j = 0; j < 4; j++) {
                    int n0 = wn*32 + j*8 + grp;
                    uint32_t v0 = Bsu[n0*ASTRIDE + kb+tig];
                    uint32_t v1 = Bsu[n0*ASTRIDE + kb+tig+4];
                    bf[j][0] = CVTB ? f2tf(__uint_as_float(v0)) : v0;
                    bf[j][1] = CVTB ? f2tf(__uint_as_float(v1)) : v1;
                }
            }
#pragma unroll
            for (int i = 0; i < 4; i++)
#pragma unroll
                for (int j = 0; j < 4; j++)
                    mma_tf32(acc[i][j], af[i][0], af[i][1], af[i][2], af[i][3],
                             bf[j][0], bf[j][1]);
        }
        prefetch(t + 2); cp_commit();
    }

    const float* csb = colscale ? (colscale + (long)blockIdx.z * N) : nullptr;
    const float* db  = dsub ? (dsub + (long)blockIdx.z * c_bat) : nullptr;

#pragma unroll
    for (int i = 0; i < 4; i++) {
        int mg = bm + wm*64 + i*16 + grp;
        float bi0 = bias ? bias[mg]   : 0.f;
        float bi1 = bias ? bias[mg+8] : 0.f;
        if (bias2) {
            bi0 += bias2[(long)blockIdx.z*M + mg];
            bi1 += bias2[(long)blockIdx.z*M + mg+8];
        }
        float rm0 = -3.402823466e38f, rm1 = -3.402823466e38f;
#pragma unroll
        for (int j = 0; j < 4; j++) {
            int ng = bn + wn*32 + j*8 + tig*2;
            float2 v0, v1;
            v0.x = acc[i][j][0] + bi0; v0.y = acc[i][j][1] + bi0;
            v1.x = acc[i][j][2] + bi1; v1.y = acc[i][j][3] + bi1;
            if (relu) {
                v0.x = fmaxf(v0.x, 0.f); v0.y = fmaxf(v0.y, 0.f);
                v1.x = fmaxf(v1.x, 0.f); v1.y = fmaxf(v1.y, 0.f);
            }
            if (csb) {
                float2 c2 = *(const float2*)(csb + ng);
                float s0 = 1.f / (1e-9f + c2.x), s1 = 1.f / (1e-9f + c2.y);
                v0.x *= s0; v0.y *= s1; v1.x *= s0; v1.y *= s1;
            }
            if (db) {
                float2 d0 = *(const float2*)&db[(long)mg*N + ng];
                float2 d1 = *(const float2*)&db[(long)(mg+8)*N + ng];
                v0.x = d0.x - v0.x; v0.y = d0.y - v0.y;
                v1.x = d1.x - v1.x; v1.y = d1.y - v1.y;
            }
            if (RNDC) {
                v0.x = rnd(v0.x); v0.y = rnd(v0.y);
                v1.x = rnd(v1.x); v1.y = rnd(v1.y);
            }
            if (amax) {
                rm0 = fmaxf(rm0, fmaxf(v0.x, v0.y));
                rm1 = fmaxf(rm1, fmaxf(v1.x, v1.y));
            }
            if (Cb) {
                *(float2*)&Cb[(long)mg*N + ng]     = v0;
                *(float2*)&Cb[(long)(mg+8)*N + ng] = v1;
            }
        }
        if (amax) {
            rm0 = fmaxf(rm0, __shfl_xor_sync(0xffffffffu, rm0, 1));
            rm0 = fmaxf(rm0, __shfl_xor_sync(0xffffffffu, rm0, 2));
            rm1 = fmaxf(rm1, __shfl_xor_sync(0xffffffffu, rm1, 1));
            rm1 = fmaxf(rm1, __shfl_xor_sync(0xffffffffu, rm1, 2));
            if (tig == 0) {
                unsigned int* ab = amax + (long)blockIdx.z * M;
                atomicMax(&ab[mg],   fenc(rm0));
                atomicMax(&ab[mg+8], fenc(rm1));
            }
        }
    }
}

// ---------------- init atomic-max scratch ----------------
__global__ void initmax_k(unsigned int* __restrict__ gmu, unsigned int* __restrict__ omaxu)
{
    int i = blockIdx.x*256 + threadIdx.x;
    if (i < BATCH*256) gmu[i] = 0u;
    if (i < BATCH*1024) omaxu[i] = 0u;
}

// ---------------- one-shot tf32 rounding of weights (w3: packed lower half) ----------------
#define N4_W2  8192
#define N4_W3L 32768
#define N4_W4  131072
#define N4_WQK 16384
#define N4_WV  65536
#define N4_WT  65536
#define N4_TOT (N4_W2 + N4_W3L + N4_W4 + N4_WQK + N4_WV + N4_WT)
__global__ void rndall_k(const float4* w2, const float4* w3, const float4* w4,
                         const float4* wqk, const float4* wv, const float4* wt,
                         float4* w2r, float4* w3l, float4* w4r,
                         float4* wqkr, float4* wvr, float4* wtr)
{
    int i = blockIdx.x*256 + threadIdx.x;
    if (i >= N4_TOT) return;
    float4 v; float4* d;
    if (i < N4_W2) { v = w2[i]; d = w2r + i; }
    else if (i < N4_W2 + N4_W3L) {
        int j = i - N4_W2;
        int m = j >> 6, kq = j & 63;
        v = w3[m*128 + kq];
        d = w3l + j;
    }
    else if (i < N4_W2 + N4_W3L + N4_W4) { int j = i - (N4_W2+N4_W3L); v = w4[j]; d = w4r + j; }
    else if (i < N4_W2 + N4_W3L + N4_W4 + N4_WQK) { int j = i - (N4_W2+N4_W3L+N4_W4); v = wqk[j]; d = wqkr + j; }
    else if (i < N4_W2 + N4_W3L + N4_W4 + N4_WQK + N4_WV) { int j = i - (N4_W2+N4_W3L+N4_W4+N4_WQK); v = wv[j]; d = wvr + j; }
    else { int j = i - (N4_W2+N4_W3L+N4_W4+N4_WQK+N4_WV); v = wt[j]; d = wtr + j; }
    v.x = rnd(v.x); v.y = rnd(v.y); v.z = rnd(v.z); v.w = rnd(v.w);
    *d = v;
}

// ---------------- vb[b][m] = sum_c rnd(w3[m][256+c]) * gm[b][c] ----------------
__global__ void vbias_k(const float* __restrict__ w3, const unsigned int* __restrict__ gmu,
                        float* __restrict__ vb)
{
    int warp = threadIdx.x >> 5, lane = threadIdx.x & 31;
    int m = blockIdx.x*8 + warp;
    int b = blockIdx.y;
    const float* wrow = w3 + (long)m*512 + 256;
    float s = 0.f;
#pragma unroll
    for (int j = 0; j < 8; j++) {
        int c = lane + 32*j;
        s += rnd(wrow[c]) * fdec(gmu[b*256 + c]);
    }
#pragma unroll
    for (int o = 16; o > 0; o >>= 1) s += __shfl_xor_sync(0xffffffffu, s, o);
    if (lane == 0) vb[b*512 + m] = s;
}

// ---------------- positional encoding (24 ch, rounded) ----------------
__global__ void posenc_k(const float* __restrict__ x, float* __restrict__ h24)
{
    int idx = blockIdx.x*blockDim.x + threadIdx.x;
    if (idx >= BATCH*3*NPTS) return;
    int n = idx % NPTS; int r = idx / NPTS;
    int dim = r % 3, b = r / 3;
    float t = x[((long)b*3 + dim)*NPTS + n];
    float* o = h24 + (long)b*24*NPTS + n;
    o[(long)(dim     )*NPTS] = rnd(t);
    o[(long)(3  + dim)*NPTS] = rnd(sinf(t));
    o[(long)(6  + dim)*NPTS] = rnd(cosf(t));
    o[(long)(9  + dim)*NPTS] = rnd(sinf(2.f*t));
    o[(long)(12 + dim)*NPTS] = rnd(cosf(2.f*t));
    o[(long)(15 + dim)*NPTS] = rnd(sinf(4.f*t));
    o[(long)(18 + dim)*NPTS] = rnd(cosf(4.f*t));
    o[(long)(21 + dim)*NPTS] = 0.f;
}

// ---------------- pad+round w1 [128,21] -> [128,24] ----------------
__global__ void w1pad_k(const float* __restrict__ w1, float* __restrict__ w1p)
{
    int i = blockIdx.x*256 + threadIdx.x;
    if (i >= 128*24) return;
    int m = i / 24, k = i % 24;
    w1p[i] = (k < 21) ? rnd(w1[m*21 + k]) : 0.f;
}

// ---------------- transpose qk [128,N] -> qkT [N,128] ----------------
__global__ void tqk_k(const float* __restrict__ qk, float* __restrict__ qkT)
{
    __shared__ float s[32][33];
    int b = blockIdx.z;
    int n0 = blockIdx.x*32, c0 = blockIdx.y*32;
    const float* src = qk + (long)b*128*NPTS;
    float*       dst = qkT + (long)b*NPTS*128;
    int x = threadIdx.x, y = threadIdx.y;
#pragma unroll
    for (int i = 0; i < 4; i++)
        s[y+8*i][x] = src[(long)(c0+y+8*i)*NPTS + n0+x];
    __syncthreads();
#pragma unroll
    for (int i = 0; i < 4; i++)
        dst[(long)(n0+y+8*i)*128 + c0+x] = s[x][y+8*i];
}

// ---------------- warp-per-row softmax: 8 rows/block, MLP-16, shfl-only ----------------
__global__ __launch_bounds__(256)
void softmax_k(float* __restrict__ attn)
{
    int warp = threadIdx.x >> 5, lane = threadIdx.x & 31;
    size_t row = (size_t)blockIdx.x*8 + warp;
    float4* p = (float4*)(attn + row * (size_t)NPTS);
    float4 v[16];
#pragma unroll
    for (int i = 0; i < 16; i++) v[i] = p[lane + 32*i];
    float m = -3.402823466e38f;
#pragma unroll
    for (int i = 0; i < 16; i++)
        m = fmaxf(m, fmaxf(fmaxf(v[i].x, v[i].y), fmaxf(v[i].z, v[i].w)));
#pragma unroll
    for (int o = 16; o > 0; o >>= 1) m = fmaxf(m, __shfl_xor_sync(0xffffffffu, m, o));
    float s = 0.f;
#pragma unroll
    for (int i = 0; i < 16; i++) {
        v[i].x = __expf(v[i].x - m); v[i].y = __expf(v[i].y - m);
        v[i].z = __expf(v[i].z - m); v[i].w = __expf(v[i].w - m);
        s += v[i].x + v[i].y + v[i].z + v[i].w;
    }
#pragma unroll
    for (int o = 16; o > 0; o >>= 1) s += __shfl_xor_sync(0xffffffffu, s, o);
    float inv = 1.f / s;
#pragma unroll
    for (int i = 0; i < 16; i++) {
        v[i].x = rnd(v[i].x * inv); v[i].y = rnd(v[i].y * inv);
        v[i].z = rnd(v[i].z * inv); v[i].w = rnd(v[i].w * inv);
        p[lane + 32*i] = v[i];
    }
}

// ---------------- colsum: float4, q-split partials (deterministic) ----------------
__global__ void colsum_k(const float* __restrict__ attn, float* __restrict__ cspart)
{
    int k4 = blockIdx.x*256 + threadIdx.x;
    int qc = blockIdx.y, b = blockIdx.z;
    const float4* p = (const float4*)(attn + (size_t)b*NPTS*NPTS) + k4;
    float4 s = make_float4(0.f, 0.f, 0.f, 0.f);
    int q0 = qc * (NPTS/QSPLIT);
#pragma unroll 8
    for (int q = q0; q < q0 + NPTS/QSPLIT; q++) {
        float4 v = p[(size_t)q * (NPTS/4)];
        s.x += v.x; s.y += v.y; s.z += v.z; s.w += v.w;
    }
    ((float4*)cspart)[((size_t)qc*BATCH + b)*(NPTS/4) + k4] = s;
}

__global__ void csred_k(const float* __restrict__ cspart, float* __restrict__ cs)
{
    int i = blockIdx.x*256 + threadIdx.x;
    if (i >= BATCH*NPTS) return;
    int b = i / NPTS, k = i % NPTS;
    float s = 0.f;
#pragma unroll
    for (int qc = 0; qc < QSPLIT; qc++)
        s += cspart[((size_t)qc*BATCH + b)*NPTS + k];
    cs[i] = s;
}

// ---------------- BN batch stats per channel (float4 loads) ----------------
__global__ void bnstats_k(const float* __restrict__ d)
{
    int c = blockIdx.x;
    int t = threadIdx.x;
    double s = 0.0, s2 = 0.0;
    for (int i4 = t; i4 < BATCH*NPTS/4; i4 += 256) {
        int b = i4 / (NPTS/4), n4 = i4 % (NPTS/4);
        float4 v = ((const float4*)(d + ((long)b*512 + c)*NPTS))[n4];
        s  += (double)v.x + (double)v.y + (double)v.z + (double)v.w;
        s2 += (double)v.x*v.x + (double)v.y*v.y + (double)v.z*v.z + (double)v.w*v.w;
    }
    __shared__ double sh[256], sh2[256];
    sh[t] = s; sh2[t] = s2; __syncthreads();
    for (int o = 128; o > 0; o >>= 1) {
        if (t < o) { sh[t] += sh[t+o]; sh2[t] += sh2[t+o]; }
        __syncthreads();
    }
    if (t == 0) {
        double mu  = sh[0]  / (double)(BATCH*NPTS);
        double var = sh2[0] / (double)(BATCH*NPTS) - mu*mu;
        g_mu[c] = (float)mu;
        g_rs[c] = (float)(1.0 / sqrt(var + 1e-5));
    }
}

// ---------------- h2 = rnd(h + relu(bn(d))) (float4) ----------------
__global__ void bnapply_k(const float* __restrict__ h, const float* __restrict__ d,
                          const float* __restrict__ gamma, const float* __restrict__ beta,
                          float* __restrict__ h2)
{
    long i = (long)blockIdx.x*256 + threadIdx.x;
    if (i >= (long)BATCH*512*NPTS/4) return;
    int c = (int)((i / (NPTS/4)) % 512);
    float ga = gamma[c], mu = g_mu[c], rs = g_rs[c], be = beta[c];
    float4 dv = ((const float4*)d)[i];
    float4 hv = ((const float4*)h)[i];
    float4 r;
    r.x = rnd(hv.x + fmaxf(ga*(dv.x - mu)*rs + be, 0.f));
    r.y = rnd(hv.y + fmaxf(ga*(dv.y - mu)*rs + be, 0.f));
    r.z = rnd(hv.z + fmaxf(ga*(dv.z - mu)*rs + be, 0.f));
    r.w = rnd(hv.w + fmaxf(ga*(dv.w - mu)*rs + be, 0.f));
    ((float4*)h2)[i] = r;
}

// ---------------- decode ordered-uint maxes into fp32 output ----------------
__global__ void decout_k(const unsigned int* __restrict__ omaxu, float* __restrict__ out)
{
    int i = blockIdx.x*256 + threadIdx.x;
    if (i >= BATCH*1024) return;
    out[i] = fdec(omaxu[i]);
}

// ---------------- launch ----------------
extern "C" void kernel_launch(void* const* d_in, const int* in_sizes, int n_in,
                              void* d_out, int out_size)
{
    const float* x    = (const float*)d_in[0];
    const float* w1   = (const float*)d_in[1];
    const float* b1   = (const float*)d_in[2];
    const float* w2   = (const float*)d_in[3];
    const float* b2   = (const float*)d_in[4];
    const float* w3   = (const float*)d_in[5];
    const float* b3   = (const float*)d_in[6];
    const float* w4   = (const float*)d_in[7];
    const float* b4   = (const float*)d_in[8];
    const float* wqk  = (const float*)d_in[9];
    const float* wv   = (const float*)d_in[10];
    const float* bv   = (const float*)d_in[11];
    const float* wt   = (const float*)d_in[12];
    const float* bt   = (const float*)d_in[13];
    const float* gamma= (const float*)d_in[14];
    const float* beta = (const float*)d_in[15];
    float* out = (float*)d_out;

    static bool attr_set = false;
    if (!attr_set) {
        cudaFuncSetAttribute(mm_tc<0,0>, cudaFuncAttributeMaxDynamicSharedMemorySize, SMEM_BYTES);
        cudaFuncSetAttribute(mm_tc<0,1>, cudaFuncAttributeMaxDynamicSharedMemorySize, SMEM_BYTES);
        cudaFuncSetAttribute(mm_tc<1,1>, cudaFuncAttributeMaxDynamicSharedMemorySize, SMEM_BYTES);
        cudaFuncSetAttribute(mm_tc_big<0,0>, cudaFuncAttributeMaxDynamicSharedMemorySize, SMEM_BYTES2);
        cudaFuncSetAttribute(mm_tc_big<0,1>, cudaFuncAttributeMaxDynamicSharedMemorySize, SMEM_BYTES2);
        cudaFuncSetAttribute(mm_tc_big<1,1>, cudaFuncAttributeMaxDynamicSharedMemorySize, SMEM_BYTES2);
        attr_set = true;
    }

    float *h24,*w1p,*w2r,*w3l,*w4r,*wqkr,*wvr,*wtr,*vb;
    float *h128,*hcat,*h,*qk,*qkT,*xv,*attn,*cs,*cspart,*hmxr,*dd,*h2;
    unsigned int *gmu,*omaxu;
    cudaGetSymbolAddress((void**)&h24,  g_h24);
    cudaGetSymbolAddress((void**)&w1p,  g_w1p);
    cudaGetSymbolAddress((void**)&w2r,  g_w2r);
    cudaGetSymbolAddress((void**)&w3l,  g_w3l);
    cudaGetSymbolAddress((void**)&w4r,  g_w4r);
    cudaGetSymbolAddress((void**)&wqkr, g_wqkr);
    cudaGetSymbolAddress((void**)&wvr,  g_wvr);
    cudaGetSymbolAddress((void**)&wtr,  g_wtr);
    cudaGetSymbolAddress((void**)&vb,   g_vb);
    cudaGetSymbolAddress((void**)&h128, g_h128);
    cudaGetSymbolAddress((void**)&gmu,  g_gmu);
    cudaGetSymbolAddress((void**)&omaxu,g_omaxu);
    cudaGetSymbolAddress((void**)&hcat, g_hcat);
    cudaGetSymbolAddress((void**)&h,    g_h);
    cudaGetSymbolAddress((void**)&qk,   g_qk);
    cudaGetSymbolAddress((void**)&qkT,  g_qkT);
    cudaGetSymbolAddress((void**)&xv,   g_xv);
    cudaGetSymbolAddress((void**)&attn, g_attn);
    cudaGetSymbolAddress((void**)&cs,   g_cs);
    cudaGetSymbolAddress((void**)&cspart, g_cspart);
    cudaGetSymbolAddress((void**)&hmxr, g_hmxr);
    cudaGetSymbolAddress((void**)&dd,   g_dd);
    cudaGetSymbolAddress((void**)&h2,   g_h2);

    const long EW = (long)BATCH*512*NPTS;

    initmax_k<<<(BATCH*1024 + 255)/256, 256>>>(gmu, omaxu);
    posenc_k<<<(BATCH*3*NPTS + 255)/256, 256>>>(x, h24);
    w1pad_k<<<(128*24 + 255)/256, 256>>>(w1, w1p);
    rndall_k<<<(N4_TOT + 255)/256, 256>>>(
        (const float4*)w2, (const float4*)w3, (const float4*)w4,
        (const float4*)wqk, (const float4*)wv, (const float4*)wt,
        (float4*)w2r, (float4*)w3l, (float4*)w4r,
        (float4*)wqkr, (float4*)wvr, (float4*)wtr);

    // conv1 (24->128) + relu, rounded out  [small]
    mm_tc<0,1><<<dim3(16,1,BATCH),256,SMEM_BYTES>>>(w1p, h24, b1, nullptr, h128,
        128, NPTS, 24, 0, (long)24*NPTS, (long)128*NPTS, 1, 0, nullptr, nullptr, nullptr);
    // conv2 (128->256), rounded, hcat lower half + fused global max  [big512]
    mm_tc_big<0,1><<<dim3(16,1,BATCH),512,SMEM_BYTES2>>>(w2r, h128, b2, nullptr, hcat,
        256, NPTS, 128, 0, (long)128*NPTS, (long)512*NPTS, 0, 0, nullptr, nullptr, gmu);
    vbias_k<<<dim3(64, BATCH), 256>>>(w3, gmu, vb);
    // conv3 lower half (K=256) + vb + relu -> h  [big512]
    mm_tc_big<0,0><<<dim3(16,2,BATCH),512,SMEM_BYTES2>>>(w3l, hcat, b3, vb, h,
        512, NPTS, 256, 0, (long)512*NPTS, (long)512*NPTS, 1, 0, nullptr, nullptr, nullptr);
    // q/k projection  [small]
    mm_tc<1,1><<<dim3(16,1,BATCH),256,SMEM_BYTES>>>(wqkr, h, nullptr, nullptr, qk,
        128, NPTS, 512, 0, (long)512*NPTS, (long)128*NPTS, 0, 0, nullptr, nullptr, nullptr);
    tqk_k<<<dim3(NPTS/32, 4, BATCH), dim3(32,8)>>>(qk, qkT);
    // energy = qkT @ qk  [big512]
    mm_tc_big<0,0><<<dim3(16,8,BATCH),512,SMEM_BYTES2>>>(qkT, qk, nullptr, nullptr, attn,
        NPTS, NPTS, 128, (long)NPTS*128, (long)128*NPTS, (long)NPTS*NPTS, 0, 0,
        nullptr, nullptr, nullptr);
    softmax_k<<<BATCH*NPTS/8, 256>>>(attn);
    colsum_k<<<dim3(NPTS/4/256, QSPLIT, BATCH), 256>>>(attn, cspart);
    csred_k<<<(BATCH*NPTS + 255)/256, 256>>>(cspart, cs);
    // v projection + fused colsum scale  [big512]
    mm_tc_big<1,1><<<dim3(16,2,BATCH),512,SMEM_BYTES2>>>(wvr, h, bv, nullptr, xv,
        512, NPTS, 512, 0, (long)512*NPTS, (long)512*NPTS, 0, 0, cs, nullptr, nullptr);
    // hmxr = rnd(h - xv_scaled @ attn^T)  [big512, bT]
    mm_tc_big<0,1><<<dim3(16,2,BATCH),512,SMEM_BYTES2>>>(xv, attn, nullptr, nullptr, hmxr,
        512, NPTS, NPTS, (long)512*NPTS, (long)NPTS*NPTS, (long)512*NPTS, 0, 1,
        nullptr, h, nullptr);
    // d = wt @ (h - x_r) + bt  [big512]
    mm_tc_big<0,0><<<dim3(16,2,BATCH),512,SMEM_BYTES2>>>(wtr, hmxr, bt, nullptr, dd,
        512, NPTS, 512, 0, (long)512*NPTS, (long)512*NPTS, 0, 0, nullptr, nullptr, nullptr);
    bnstats_k<<<512, 256>>>(dd);
    bnapply_k<<<(int)((EW/4 + 255)/256), 256>>>(h, dd, gamma, beta, h2);
    // conv4 (512->1024) fused with final max  [big512]
    mm_tc_big<0,0><<<dim3(16,4,BATCH),512,SMEM_BYTES2>>>(w4r, h2, b4, nullptr, nullptr,
        1024, NPTS, 512, 0, (long)512*NPTS, 0, 0, 0, nullptr, nullptr, omaxu);
    decout_k<<<(BATCH*1024 + 255)/256, 256>>>(omaxu, out);
}

// round 13
// speedup vs baseline: 1.1049x; 1.0797x over previous
#include <cuda_runtime.h>
#include <math.h>
#include <stdint.h>

#define BATCH 16
#define NPTS  2048
#define BM 128
#define BN 128
#define BKT 32
#define ASTRIDE 36      // (36*grp+tig) mod 32 = 4*grp+tig -> all 32 banks distinct
#define BSTRIDE 136     // also used as m-stride for aT A-tiles (8*tig+grp banks)
#define STAGE_FLOATS (128*ASTRIDE + 128*ASTRIDE)   // 9216
#define SMEM_BYTES (3 * STAGE_FLOATS * 4)          // 110592

// ---------------- scratch (device globals) ----------------
__device__ float g_h24 [(size_t)BATCH*24*NPTS];
__device__ float g_w1p [128*24];
__device__ float g_w2r [256*128];
__device__ float g_w3l [512*256];
__device__ float g_w4r [1024*512];
__device__ float g_wqkr[128*512];
__device__ float g_wvr [512*512];
__device__ float g_wtr [512*512];
__device__ float g_vb  [BATCH*512];
__device__ float g_h128[(size_t)BATCH*128*NPTS];
__device__ unsigned int g_gmu  [BATCH*256];
__device__ unsigned int g_omaxu[BATCH*1024];
__device__ float g_hcat[(size_t)BATCH*512*NPTS];
__device__ float g_h   [(size_t)BATCH*512*NPTS];
__device__ float g_qk  [(size_t)BATCH*128*NPTS];
__device__ float g_xv  [(size_t)BATCH*512*NPTS];
__device__ float g_attn[(size_t)BATCH*NPTS*NPTS];   // 256 MB
__device__ float g_cs  [BATCH*NPTS];
__device__ float g_cspart[(size_t)BATCH*256*NPTS];  // 33.5 MB: per-8-row-block partials
__device__ float g_hmxr[(size_t)BATCH*512*NPTS];
__device__ float g_dd  [(size_t)BATCH*512*NPTS];
__device__ float g_mu  [512];
__device__ float g_rs  [512];
__device__ float g_h2  [(size_t)BATCH*512*NPTS];

// ---------------- helpers ----------------
__device__ __forceinline__ uint32_t f2tf(float f){
    uint32_t u;
    asm("cvt.rna.tf32.f32 %0, %1;" : "=r"(u) : "f"(f));
    return u;
}
__device__ __forceinline__ float rnd(float f){ return __uint_as_float(f2tf(f)); }

__device__ __forceinline__ unsigned int fenc(float f){
    unsigned int u = __float_as_uint(f);
    return (u >> 31) ? ~u : (u | 0x80000000u);
}
__device__ __forceinline__ float fdec(unsigned int u){
    return __uint_as_float((u >> 31) ? (u ^ 0x80000000u) : ~u);
}

__device__ __forceinline__ void mma_tf32(float c[4], uint32_t a0, uint32_t a1,
                                         uint32_t a2, uint32_t a3,
                                         uint32_t b0, uint32_t b1){
    asm volatile(
        "mma.sync.aligned.m16n8k8.row.col.f32.tf32.tf32.f32 "
        "{%0,%1,%2,%3}, {%4,%5,%6,%7}, {%8,%9}, {%0,%1,%2,%3};"
        : "+f"(c[0]), "+f"(c[1]), "+f"(c[2]), "+f"(c[3])
        : "r"(a0), "r"(a1), "r"(a2), "r"(a3), "r"(b0), "r"(b1));
}

__device__ __forceinline__ void cp16(uint32_t dst, const float* src, int sz){
    asm volatile("cp.async.cg.shared.global [%0], [%1], 16, %2;"
                 :: "r"(dst), "l"(src), "r"(sz));
}
__device__ __forceinline__ void cp_commit(){ asm volatile("cp.async.commit_group;"); }
__device__ __forceinline__ void cp_wait1(){ asm volatile("cp.async.wait_group 1;"); }

// ---------------- TF32 TC GEMM (R10 core) + aT mode + fused epilogues ----------------
// C[b][m][n] = sum_k A(m,k)*B(k,n) (+bias[m]) (+bias2[b][m]) (+relu)
//              (*1/(1e-9+colscale[b][n]))  [dsub: C = dsub - C]  (RNDC round)
// A: if !ATM, row-major [M,K] k-contig; if ATM, A(m,k)=Ab[k*a_ld + m] (m-contig).
// B: !bT -> [K,N] n-contig ; bT -> [N,K] k-contig
// amax: atomicMax row-max into amax[b*M+m]. C may be null (skip store).
template<int CVTB, int RNDC, int ATM>
__global__ __launch_bounds__(256, 2)
void mm_tc(const float* __restrict__ A, const float* __restrict__ B,
           const float* __restrict__ bias, const float* __restrict__ bias2,
           float* __restrict__ C,
           int M, int N, int K,
           long a_bat, long a_ld, long b_bat, long c_bat, int relu, int bT,
           const float* __restrict__ colscale, const float* __restrict__ dsub,
           unsigned int* __restrict__ amax)
{
    extern __shared__ float sm[];
    const float* Ab = A + (long)blockIdx.z * a_bat;
    const float* Bb = B + (long)blockIdx.z * b_bat;
    float*       Cb = C ? (C + (long)blockIdx.z * c_bat) : nullptr;
    const int bm = blockIdx.y * BM, bn = blockIdx.x * BN;
    const int tid = threadIdx.x;
    const int lane = tid & 31, wid = tid >> 5;
    const int wm = wid >> 2, wn = wid & 3;
    const int grp = lane >> 2, tig = lane & 3;
    const int ntiles = (K + BKT - 1) / BKT;
    const uint32_t sbase = (uint32_t)__cvta_generic_to_shared(sm);

    float acc[4][4][4];
#pragma unroll
    for (int i = 0; i < 4; i++)
#pragma unroll
        for (int j = 0; j < 4; j++)
#pragma unroll
            for (int r = 0; r < 4; r++) acc[i][j][r] = 0.f;

    auto prefetch = [&](int t){
        if (t >= ntiles) return;
        const int buf = t % 3;
        const uint32_t as0 = sbase + (uint32_t)(buf * STAGE_FLOATS) * 4u;
        const uint32_t bs0 = as0 + (uint32_t)(128 * ASTRIDE) * 4u;
        const int k0 = t * BKT;
        if (!ATM) {
            // A tile [m][k]: 128 rows x 32 k
#pragma unroll
            for (int i = 0; i < 4; i++) {
                int idx = tid + i*256;
                int mm = idx >> 3, kq = (idx & 7) << 2;
                long kg = (long)k0 + kq;
                long rem = ((long)K - kg) * 4;
                int sz = rem >= 16 ? 16 : (rem > 0 ? (int)rem : 0);
                const float* src = (sz > 0) ? (Ab + (long)(bm + mm)*K + kg) : Ab;
                cp16(as0 + (uint32_t)(mm*ASTRIDE + kq)*4u, src, sz);
            }
        } else {
            // A tile [k][m]: 32 k-rows x 128 m (m-contiguous global)
#pragma unroll
            for (int i = 0; i < 4; i++) {
                int idx = tid + i*256;
                int kk = idx >> 5, mq = (idx & 31) << 2;
                long kg = (long)k0 + kk;
                int sz = (kg < K) ? 16 : 0;
                const float* src = (sz > 0) ? (Ab + kg*a_ld + (bm + mq)) : Ab;
                cp16(as0 + (uint32_t)(kk*BSTRIDE + mq)*4u, src, sz);
            }
        }
        if (!bT) {
#pragma unroll
            for (int i = 0; i < 4; i++) {
                int idx = tid + i*256;
                int kk = idx >> 5, nq = (idx & 31) << 2;
                long kg = (long)k0 + kk;
                int sz = (kg < K) ? 16 : 0;
                const float* src = (sz > 0) ? (Bb + kg*(long)N + (bn + nq)) : Bb;
                cp16(bs0 + (uint32_t)(kk*BSTRIDE + nq)*4u, src, sz);
            }
        } else {
#pragma unroll
            for (int i = 0; i < 4; i++) {
                int idx = tid + i*256;
                int nn = idx >> 3, kq = (idx & 7) << 2;
                long kg = (long)k0 + kq;
                long rem = ((long)K - kg) * 4;
                int sz = rem >= 16 ? 16 : (rem > 0 ? (int)rem : 0);
                const float* src = (sz > 0) ? (Bb + (long)(bn + nn)*K + kg) : Bb;
                cp16(bs0 + (uint32_t)(nn*ASTRIDE + kq)*4u, src, sz);
            }
        }
    };

    prefetch(0); cp_commit();
    prefetch(1); cp_commit();

    for (int t = 0; t < ntiles; t++) {
        cp_wait1();
        __syncthreads();
        const float* As = sm + (t % 3) * STAGE_FLOATS;
        const float* Bs = As + 128 * ASTRIDE;
        const uint32_t* Asu = (const uint32_t*)As;
        const uint32_t* Bsu = (const uint32_t*)Bs;

#pragma unroll
        for (int ks = 0; ks < 4; ks++) {
            const int kb = ks * 8;
            uint32_t af[4][4], bf[4][2];
#pragma unroll
            for (int i = 0; i < 4; i++) {
                int m0 = wm*64 + i*16 + grp;
                if (!ATM) {
                    const uint32_t* r0 = Asu + m0*ASTRIDE;
                    const uint32_t* r1 = r0 + 8*ASTRIDE;
                    af[i][0] = r0[kb+tig];
                    af[i][1] = r1[kb+tig];
                    af[i][2] = r0[kb+tig+4];
                    af[i][3] = r1[kb+tig+4];
                } else {
                    af[i][0] = Asu[(kb+tig  )*BSTRIDE + m0];
                    af[i][1] = Asu[(kb+tig  )*BSTRIDE + m0+8];
                    af[i][2] = Asu[(kb+tig+4)*BSTRIDE + m0];
                    af[i][3] = Asu[(kb+tig+4)*BSTRIDE + m0+8];
                }
            }
            if (!bT) {
#pragma unroll
                for (int j = 0; j < 4; j++) {
                    int n0 = wn*32 + j*8 + grp;
                    uint32_t v0 = Bsu[(kb+tig)*BSTRIDE + n0];
                    uint32_t v1 = Bsu[(kb+tig+4)*BSTRIDE + n0];
                    bf[j][0] = CVTB ? f2tf(__uint_as_float(v0)) : v0;
                    bf[j][1] = CVTB ? f2tf(__uint_as_float(v1)) : v1;
                }
            } else {
#pragma unroll
                for (int j = 0; j < 4; j++) {
                    int n0 = wn*32 + j*8 + grp;
                    uint32_t v0 = Bsu[n0*ASTRIDE + kb+tig];
                    uint32_t v1 = Bsu[n0*ASTRIDE + kb+tig+4];
                    bf[j][0] = CVTB ? f2tf(__uint_as_float(v0)) : v0;
                    bf[j][1] = CVTB ? f2tf(__uint_as_float(v1)) : v1;
                }
            }
#pragma unroll
            for (int i = 0; i < 4; i++)
#pragma unroll
                for (int j = 0; j < 4; j++)
                    mma_tf32(acc[i][j], af[i][0], af[i][1], af[i][2], af[i][3],
                             bf[j][0], bf[j][1]);
        }
        prefetch(t + 2); cp_commit();
    }

    const float* csb = colscale ? (colscale + (long)blockIdx.z * N) : nullptr;
    const float* db  = dsub ? (dsub + (long)blockIdx.z * c_bat) : nullptr;

#pragma unroll
    for (int i = 0; i < 4; i++) {
        int mg = bm + wm*64 + i*16 + grp;
        float bi0 = bias ? bias[mg]   : 0.f;
        float bi1 = bias ? bias[mg+8] : 0.f;
        if (bias2) {
            bi0 += bias2[(long)blockIdx.z*M + mg];
            bi1 += bias2[(long)blockIdx.z*M + mg+8];
        }
        float rm0 = -3.402823466e38f, rm1 = -3.402823466e38f;
#pragma unroll
        for (int j = 0; j < 4; j++) {
            int ng = bn + wn*32 + j*8 + tig*2;
            float2 v0, v1;
            v0.x = acc[i][j][0] + bi0; v0.y = acc[i][j][1] + bi0;
            v1.x = acc[i][j][2] + bi1; v1.y = acc[i][j][3] + bi1;
            if (relu) {
                v0.x = fmaxf(v0.x, 0.f); v0.y = fmaxf(v0.y, 0.f);
                v1.x = fmaxf(v1.x, 0.f); v1.y = fmaxf(v1.y, 0.f);
            }
            if (csb) {
                float2 c2 = *(const float2*)(csb + ng);
                float s0 = 1.f / (1e-9f + c2.x), s1 = 1.f / (1e-9f + c2.y);
                v0.x *= s0; v0.y *= s1; v1.x *= s0; v1.y *= s1;
            }
            if (db) {
                float2 d0 = *(const float2*)&db[(long)mg*N + ng];
                float2 d1 = *(const float2*)&db[(long)(mg+8)*N + ng];
                v0.x = d0.x - v0.x; v0.y = d0.y - v0.y;
                v1.x = d1.x - v1.x; v1.y = d1.y - v1.y;
            }
            if (RNDC) {
                v0.x = rnd(v0.x); v0.y = rnd(v0.y);
                v1.x = rnd(v1.x); v1.y = rnd(v1.y);
            }
            if (amax) {
                rm0 = fmaxf(rm0, fmaxf(v0.x, v0.y));
                rm1 = fmaxf(rm1, fmaxf(v1.x, v1.y));
            }
            if (Cb) {
                *(float2*)&Cb[(long)mg*N + ng]     = v0;
                *(float2*)&Cb[(long)(mg+8)*N + ng] = v1;
            }
        }
        if (amax) {
            rm0 = fmaxf(rm0, __shfl_xor_sync(0xffffffffu, rm0, 1));
            rm0 = fmaxf(rm0, __shfl_xor_sync(0xffffffffu, rm0, 2));
            rm1 = fmaxf(rm1, __shfl_xor_sync(0xffffffffu, rm1, 1));
            rm1 = fmaxf(rm1, __shfl_xor_sync(0xffffffffu, rm1, 2));
            if (tig == 0) {
                unsigned int* ab = amax + (long)blockIdx.z * M;
                atomicMax(&ab[mg],   fenc(rm0));
                atomicMax(&ab[mg+8], fenc(rm1));
            }
        }
    }
}

// ---------------- init atomic-max scratch ----------------
__global__ void initmax_k(unsigned int* __restrict__ gmu, unsigned int* __restrict__ omaxu)
{
    int i = blockIdx.x*256 + threadIdx.x;
    if (i < BATCH*256) gmu[i] = 0u;
    if (i < BATCH*1024) omaxu[i] = 0u;
}

// ---------------- one-shot tf32 rounding of weights (w3: packed lower half) ----------------
#define N4_W2  8192
#define N4_W3L 32768
#define N4_W4  131072
#define N4_WQK 16384
#define N4_WV  65536
#define N4_WT  65536
#define N4_TOT (N4_W2 + N4_W3L + N4_W4 + N4_WQK + N4_WV + N4_WT)
__global__ void rndall_k(const float4* w2, const float4* w3, const float4* w4,
                         const float4* wqk, const float4* wv, const float4* wt,
                         float4* w2r, float4* w3l, float4* w4r,
                         float4* wqkr, float4* wvr, float4* wtr)
{
    int i = blockIdx.x*256 + threadIdx.x;
    if (i >= N4_TOT) return;
    float4 v; float4* d;
    if (i < N4_W2) { v = w2[i]; d = w2r + i; }
    else if (i < N4_W2 + N4_W3L) {
        int j = i - N4_W2;
        int m = j >> 6, kq = j & 63;
        v = w3[m*128 + kq];
        d = w3l + j;
    }
    else if (i < N4_W2 + N4_W3L + N4_W4) { int j = i - (N4_W2+N4_W3L); v = w4[j]; d = w4r + j; }
    else if (i < N4_W2 + N4_W3L + N4_W4 + N4_WQK) { int j = i - (N4_W2+N4_W3L+N4_W4); v = wqk[j]; d = wqkr + j; }
    else if (i < N4_W2 + N4_W3L + N4_W4 + N4_WQK + N4_WV) { int j = i - (N4_W2+N4_W3L+N4_W4+N4_WQK); v = wv[j]; d = wvr + j; }
    else { int j = i - (N4_W2+N4_W3L+N4_W4+N4_WQK+N4_WV); v = wt[j]; d = wtr + j; }
    v.x = rnd(v.x); v.y = rnd(v.y); v.z = rnd(v.z); v.w = rnd(v.w);
    *d = v;
}

// ---------------- vb[b][m] = sum_c rnd(w3[m][256+c]) * gm[b][c] ----------------
__global__ void vbias_k(const float* __restrict__ w3, const unsigned int* __restrict__ gmu,
                        float* __restrict__ vb)
{
    int warp = threadIdx.x >> 5, lane = threadIdx.x & 31;
    int m = blockIdx.x*8 + warp;
    int b = blockIdx.y;
    const float* wrow = w3 + (long)m*512 + 256;
    float s = 0.f;
#pragma unroll
    for (int j = 0; j < 8; j++) {
        int c = lane + 32*j;
        s += rnd(wrow[c]) * fdec(gmu[b*256 + c]);
    }
#pragma unroll
    for (int o = 16; o > 0; o >>= 1) s += __shfl_xor_sync(0xffffffffu, s, o);
    if (lane == 0) vb[b*512 + m] = s;
}

// ---------------- positional encoding (24 ch, rounded) ----------------
__global__ void posenc_k(const float* __restrict__ x, float* __restrict__ h24)
{
    int idx = blockIdx.x*blockDim.x + threadIdx.x;
    if (idx >= BATCH*3*NPTS) return;
    int n = idx % NPTS; int r = idx / NPTS;
    int dim = r % 3, b = r / 3;
    float t = x[((long)b*3 + dim)*NPTS + n];
    float* o = h24 + (long)b*24*NPTS + n;
    o[(long)(dim     )*NPTS] = rnd(t);
    o[(long)(3  + dim)*NPTS] = rnd(sinf(t));
    o[(long)(6  + dim)*NPTS] = rnd(cosf(t));
    o[(long)(9  + dim)*NPTS] = rnd(sinf(2.f*t));
    o[(long)(12 + dim)*NPTS] = rnd(cosf(2.f*t));
    o[(long)(15 + dim)*NPTS] = rnd(sinf(4.f*t));
    o[(long)(18 + dim)*NPTS] = rnd(cosf(4.f*t));
    o[(long)(21 + dim)*NPTS] = 0.f;
}

// ---------------- pad+round w1 [128,21] -> [128,24] ----------------
__global__ void w1pad_k(const float* __restrict__ w1, float* __restrict__ w1p)
{
    int i = blockIdx.x*256 + threadIdx.x;
    if (i >= 128*24) return;
    int m = i / 24, k = i % 24;
    w1p[i] = (k < 21) ? rnd(w1[m*21 + k]) : 0.f;
}

// ---------------- warp-per-row softmax + fused per-block colsum partials ----------------
__global__ __launch_bounds__(256)
void softmax_k(float* __restrict__ attn, float* __restrict__ cspart)
{
    __shared__ float4 csm4[NPTS/4];       // 8 KB: per-block column partial sums
    int warp = threadIdx.x >> 5, lane = threadIdx.x & 31;
    size_t row = (size_t)blockIdx.x*8 + warp;
    float4* p = (float4*)(attn + row * (size_t)NPTS);
    float4 v[16];
#pragma unroll
    for (int i = 0; i < 16; i++) v[i] = p[lane + 32*i];
    float m = -3.402823466e38f;
#pragma unroll
    for (int i = 0; i < 16; i++)
        m = fmaxf(m, fmaxf(fmaxf(v[i].x, v[i].y), fmaxf(v[i].z, v[i].w)));
#pragma unroll
    for (int o = 16; o > 0; o >>= 1) m = fmaxf(m, __shfl_xor_sync(0xffffffffu, m, o));
    float s = 0.f;
#pragma unroll
    for (int i = 0; i < 16; i++) {
        v[i].x = __expf(v[i].x - m); v[i].y = __expf(v[i].y - m);
        v[i].z = __expf(v[i].z - m); v[i].w = __expf(v[i].w - m);
        s += v[i].x + v[i].y + v[i].z + v[i].w;
    }
#pragma unroll
    for (int o = 16; o > 0; o >>= 1) s += __shfl_xor_sync(0xffffffffu, s, o);
    float inv = 1.f / s;
#pragma unroll
    for (int i = 0; i < 16; i++) {
        v[i].x = rnd(v[i].x * inv); v[i].y = rnd(v[i].y * inv);
        v[i].z = rnd(v[i].z * inv); v[i].w = rnd(v[i].w * inv);
        p[lane + 32*i] = v[i];
    }
    // deterministic per-block column partials: warps add in fixed order
#pragma unroll
    for (int w = 0; w < 8; w++) {
        if (warp == w) {
#pragma unroll
            for (int i = 0; i < 16; i++) {
                if (w == 0) csm4[lane + 32*i] = v[i];
                else {
                    float4 a = csm4[lane + 32*i];
                    a.x += v[i].x; a.y += v[i].y; a.z += v[i].z; a.w += v[i].w;
                    csm4[lane + 32*i] = a;
                }
            }
        }
        __syncthreads();
    }
    float4* cp = (float4*)(cspart + (size_t)blockIdx.x * NPTS);
#pragma unroll
    for (int i = 0; i < 2; i++)
        cp[threadIdx.x + 256*i] = csm4[threadIdx.x + 256*i];
}

// ---------------- reduce 256 per-block partials -> cs[b][k] ----------------
__global__ void csred_k(const float* __restrict__ cspart, float* __restrict__ cs)
{
    int i = blockIdx.x*256 + threadIdx.x;
    if (i >= BATCH*NPTS) return;
    int b = i / NPTS, k = i % NPTS;
    const float* p = cspart + (size_t)b*256*NPTS + k;
    float s = 0.f;
#pragma unroll 8
    for (int j = 0; j < 256; j++) s += p[(size_t)j*NPTS];
    cs[i] = s;
}

// ---------------- BN batch stats per channel (float4 loads) ----------------
__global__ void bnstats_k(const float* __restrict__ d)
{
    int c = blockIdx.x;
    int t = threadIdx.x;
    double s = 0.0, s2 = 0.0;
    for (int i4 = t; i4 < BATCH*NPTS/4; i4 += 256) {
        int b = i4 / (NPTS/4), n4 = i4 % (NPTS/4);
        float4 v = ((const float4*)(d + ((long)b*512 + c)*NPTS))[n4];
        s  += (double)v.x + (double)v.y + (double)v.z + (double)v.w;
        s2 += (double)v.x*v.x + (double)v.y*v.y + (double)v.z*v.z + (double)v.w*v.w;
    }
    __shared__ double sh[256], sh2[256];
    sh[t] = s; sh2[t] = s2; __syncthreads();
    for (int o = 128; o > 0; o >>= 1) {
        if (t < o) { sh[t] += sh[t+o]; sh2[t] += sh2[t+o]; }
        __syncthreads();
    }
    if (t == 0) {
        double mu  = sh[0]  / (double)(BATCH*NPTS);
        double var = sh2[0] / (double)(BATCH*NPTS) - mu*mu;
        g_mu[c] = (float)mu;
        g_rs[c] = (float)(1.0 / sqrt(var + 1e-5));
    }
}

// ---------------- h2 = rnd(h + relu(bn(d))) (float4) ----------------
__global__ void bnapply_k(const float* __restrict__ h, const float* __restrict__ d,
                          const float* __restrict__ gamma, const float* __restrict__ beta,
                          float* __restrict__ h2)
{
    long i = (long)blockIdx.x*256 + threadIdx.x;
    if (i >= (long)BATCH*512*NPTS/4) return;
    int c = (int)((i / (NPTS/4)) % 512);
    float ga = gamma[c], mu = g_mu[c], rs = g_rs[c], be = beta[c];
    float4 dv = ((const float4*)d)[i];
    float4 hv = ((const float4*)h)[i];
    float4 r;
    r.x = rnd(hv.x + fmaxf(ga*(dv.x - mu)*rs + be, 0.f));
    r.y = rnd(hv.y + fmaxf(ga*(dv.y - mu)*rs + be, 0.f));
    r.z = rnd(hv.z + fmaxf(ga*(dv.z - mu)*rs + be, 0.f));
    r.w = rnd(hv.w + fmaxf(ga*(dv.w - mu)*rs + be, 0.f));
    ((float4*)h2)[i] = r;
}

// ---------------- decode ordered-uint maxes into fp32 output ----------------
__global__ void decout_k(const unsigned int* __restrict__ omaxu, float* __restrict__ out)
{
    int i = blockIdx.x*256 + threadIdx.x;
    if (i >= BATCH*1024) return;
    out[i] = fdec(omaxu[i]);
}

// ---------------- launch ----------------
extern "C" void kernel_launch(void* const* d_in, const int* in_sizes, int n_in,
                              void* d_out, int out_size)
{
    const float* x    = (const float*)d_in[0];
    const float* w1   = (const float*)d_in[1];
    const float* b1   = (const float*)d_in[2];
    const float* w2   = (const float*)d_in[3];
    const float* b2   = (const float*)d_in[4];
    const float* w3   = (const float*)d_in[5];
    const float* b3   = (const float*)d_in[6];
    const float* w4   = (const float*)d_in[7];
    const float* b4   = (const float*)d_in[8];
    const float* wqk  = (const float*)d_in[9];
    const float* wv   = (const float*)d_in[10];
    const float* bv   = (const float*)d_in[11];
    const float* wt   = (const float*)d_in[12];
    const float* bt   = (const float*)d_in[13];
    const float* gamma= (const float*)d_in[14];
    const float* beta = (const float*)d_in[15];
    float* out = (float*)d_out;

    static bool attr_set = false;
    if (!attr_set) {
        cudaFuncSetAttribute(mm_tc<0,0,0>, cudaFuncAttributeMaxDynamicSharedMemorySize, SMEM_BYTES);
        cudaFuncSetAttribute(mm_tc<0,1,0>, cudaFuncAttributeMaxDynamicSharedMemorySize, SMEM_BYTES);
        cudaFuncSetAttribute(mm_tc<1,1,0>, cudaFuncAttributeMaxDynamicSharedMemorySize, SMEM_BYTES);
        cudaFuncSetAttribute(mm_tc<0,0,1>, cudaFuncAttributeMaxDynamicSharedMemorySize, SMEM_BYTES);
        attr_set = true;
    }

    float *h24,*w1p,*w2r,*w3l,*w4r,*wqkr,*wvr,*wtr,*vb;
    float *h128,*hcat,*h,*qk,*xv,*attn,*cs,*cspart,*hmxr,*dd,*h2;
    unsigned int *gmu,*omaxu;
    cudaGetSymbolAddress((void**)&h24,  g_h24);
    cudaGetSymbolAddress((void**)&w1p,  g_w1p);
    cudaGetSymbolAddress((void**)&w2r,  g_w2r);
    cudaGetSymbolAddress((void**)&w3l,  g_w3l);
    cudaGetSymbolAddress((void**)&w4r,  g_w4r);
    cudaGetSymbolAddress((void**)&wqkr, g_wqkr);
    cudaGetSymbolAddress((void**)&wvr,  g_wvr);
    cudaGetSymbolAddress((void**)&wtr,  g_wtr);
    cudaGetSymbolAddress((void**)&vb,   g_vb);
    cudaGetSymbolAddress((void**)&h128, g_h128);
    cudaGetSymbolAddress((void**)&gmu,  g_gmu);
    cudaGetSymbolAddress((void**)&omaxu,g_omaxu);
    cudaGetSymbolAddress((void**)&hcat, g_hcat);
    cudaGetSymbolAddress((void**)&h,    g_h);
    cudaGetSymbolAddress((void**)&qk,   g_qk);
    cudaGetSymbolAddress((void**)&xv,   g_xv);
    cudaGetSymbolAddress((void**)&attn, g_attn);
    cudaGetSymbolAddress((void**)&cs,   g_cs);
    cudaGetSymbolAddress((void**)&cspart, g_cspart);
    cudaGetSymbolAddress((void**)&hmxr, g_hmxr);
    cudaGetSymbolAddress((void**)&dd,   g_dd);
    cudaGetSymbolAddress((void**)&h2,   g_h2);

    const long EW = (long)BATCH*512*NPTS;

    initmax_k<<<(BATCH*1024 + 255)/256, 256>>>(gmu, omaxu);
    posenc_k<<<(BATCH*3*NPTS + 255)/256, 256>>>(x, h24);
    w1pad_k<<<(128*24 + 255)/256, 256>>>(w1, w1p);
    rndall_k<<<(N4_TOT + 255)/256, 256>>>(
        (const float4*)w2, (const float4*)w3, (const float4*)w4,
        (const float4*)wqk, (const float4*)wv, (const float4*)wt,
        (float4*)w2r, (float4*)w3l, (float4*)w4r,
        (float4*)wqkr, (float4*)wvr, (float4*)wtr);

    // conv1 (24->128) + relu, rounded out
    mm_tc<0,1,0><<<dim3(16,1,BATCH),256,SMEM_BYTES>>>(w1p, h24, b1, nullptr, h128,
        128, NPTS, 24, 0, 0, (long)24*NPTS, (long)128*NPTS, 1, 0, nullptr, nullptr, nullptr);
    // conv2 (128->256), rounded, hcat lower half + fused global max
    mm_tc<0,1,0><<<dim3(16,2,BATCH),256,SMEM_BYTES>>>(w2r, h128, b2, nullptr, hcat,
        256, NPTS, 128, 0, 0, (long)128*NPTS, (long)512*NPTS, 0, 0, nullptr, nullptr, gmu);
    vbias_k<<<dim3(64, BATCH), 256>>>(w3, gmu, vb);
    // conv3 lower half (K=256) + vb + relu -> h
    mm_tc<0,0,0><<<dim3(16,4,BATCH),256,SMEM_BYTES>>>(w3l, hcat, b3, vb, h,
        512, NPTS, 256, 0, 0, (long)512*NPTS, (long)512*NPTS, 1, 0, nullptr, nullptr, nullptr);
    // q/k projection (tied weights), B=h needs cvt, rounded out
    mm_tc<1,1,0><<<dim3(16,1,BATCH),256,SMEM_BYTES>>>(wqkr, h, nullptr, nullptr, qk,
        128, NPTS, 512, 0, 0, (long)512*NPTS, (long)128*NPTS, 0, 0, nullptr, nullptr, nullptr);
    // energy = qk^T @ qk via aT mode (A m-contiguous, no transpose kernel)
    mm_tc<0,0,1><<<dim3(16,16,BATCH),256,SMEM_BYTES>>>(qk, qk, nullptr, nullptr, attn,
        NPTS, NPTS, 128, (long)128*NPTS, (long)NPTS, (long)128*NPTS, (long)NPTS*NPTS,
        0, 0, nullptr, nullptr, nullptr);
    // softmax + fused per-block column partials
    softmax_k<<<BATCH*NPTS/8, 256>>>(attn, cspart);
    csred_k<<<(BATCH*NPTS + 255)/256, 256>>>(cspart, cs);
    // v projection with fused colsum scale, rounded
    mm_tc<1,1,0><<<dim3(16,4,BATCH),256,SMEM_BYTES>>>(wvr, h, bv, nullptr, xv,
        512, NPTS, 512, 0, 0, (long)512*NPTS, (long)512*NPTS, 0, 0, cs, nullptr, nullptr);
    // hmxr = rnd(h - xv_scaled @ attn^T)
    mm_tc<0,1,0><<<dim3(16,4,BATCH),256,SMEM_BYTES>>>(xv, attn, nullptr, nullptr, hmxr,
        512, NPTS, NPTS, (long)512*NPTS, 0, (long)NPTS*NPTS, (long)512*NPTS, 0, 1,
        nullptr, h, nullptr);
    // d = wt @ (h - x_r) + bt
    mm_tc<0,0,0><<<dim3(16,4,BATCH),256,SMEM_BYTES>>>(wtr, hmxr, bt, nullptr, dd,
        512, NPTS, 512, 0, 0, (long)512*NPTS, (long)512*NPTS, 0, 0, nullptr, nullptr, nullptr);
    bnstats_k<<<512, 256>>>(dd);
    bnapply_k<<<(int)((EW/4 + 255)/256), 256>>>(h, dd, gamma, beta, h2);
    // conv4 (512->1024) fused with final max-over-N
    mm_tc<0,0,0><<<dim3(16,8,BATCH),256,SMEM_BYTES>>>(w4r, h2, b4, nullptr, nullptr,
        1024, NPTS, 512, 0, 0, (long)512*NPTS, 0, 0, 0, nullptr, nullptr, omaxu);
    decout_k<<<(BATCH*1024 + 255)/256, 256>>>(omaxu, out);
}

// round 14
// speedup vs baseline: 1.1341x; 1.0264x over previous
#include <cuda_runtime.h>
#include <math.h>
#include <stdint.h>

#define BATCH 16
#define NPTS  2048
#define BM 128
#define BN 128
#define BKT 32
#define ASTRIDE 36      // (36*grp+tig) mod 32 = 4*grp+tig -> all 32 banks distinct
#define BSTRIDE 136
#define STAGE_FLOATS (128*ASTRIDE + 128*ASTRIDE)   // 9216
#define SMEM_BYTES (3 * STAGE_FLOATS * 4)          // 110592

// ---------------- scratch (device globals) ----------------
__device__ float g_h24 [(size_t)BATCH*24*NPTS];
__device__ float g_w1p [128*24];
__device__ float g_w2r [256*128];
__device__ float g_w3l [512*256];
__device__ float g_w4r [1024*512];
__device__ float g_wqkr[128*512];
__device__ float g_wvr [512*512];
__device__ float g_wtr [512*512];
__device__ float g_vb  [BATCH*512];
__device__ float g_h128[(size_t)BATCH*128*NPTS];
__device__ unsigned int g_gmu  [BATCH*256];
__device__ unsigned int g_omaxu[BATCH*1024];
__device__ float g_hcat[(size_t)BATCH*512*NPTS];
__device__ float g_h   [(size_t)BATCH*512*NPTS];
__device__ float g_qk  [(size_t)BATCH*128*NPTS];
__device__ float g_qkT [(size_t)BATCH*NPTS*128];
__device__ float g_xv  [(size_t)BATCH*512*NPTS];
__device__ float g_attn[(size_t)BATCH*NPTS*NPTS];   // 256 MB
__device__ float g_cs  [BATCH*NPTS];
__device__ float g_cspart[(size_t)BATCH*256*NPTS];  // per-8-row-block partials
__device__ float g_hmxr[(size_t)BATCH*512*NPTS];
__device__ float g_dd  [(size_t)BATCH*512*NPTS];
__device__ float g_mu  [512];
__device__ float g_rs  [512];
__device__ float g_h2  [(size_t)BATCH*512*NPTS];

// ---------------- helpers ----------------
__device__ __forceinline__ uint32_t f2tf(float f){
    uint32_t u;
    asm("cvt.rna.tf32.f32 %0, %1;" : "=r"(u) : "f"(f));
    return u;
}
__device__ __forceinline__ float rnd(float f){ return __uint_as_float(f2tf(f)); }

__device__ __forceinline__ unsigned int fenc(float f){
    unsigned int u = __float_as_uint(f);
    return (u >> 31) ? ~u : (u | 0x80000000u);
}
__device__ __forceinline__ float fdec(unsigned int u){
    return __uint_as_float((u >> 31) ? (u ^ 0x80000000u) : ~u);
}

__device__ __forceinline__ void mma_tf32(float c[4], uint32_t a0, uint32_t a1,
                                         uint32_t a2, uint32_t a3,
                                         uint32_t b0, uint32_t b1){
    asm volatile(
        "mma.sync.aligned.m16n8k8.row.col.f32.tf32.tf32.f32 "
        "{%0,%1,%2,%3}, {%4,%5,%6,%7}, {%8,%9}, {%0,%1,%2,%3};"
        : "+f"(c[0]), "+f"(c[1]), "+f"(c[2]), "+f"(c[3])
        : "r"(a0), "r"(a1), "r"(a2), "r"(a3), "r"(b0), "r"(b1));
}

__device__ __forceinline__ void cp16(uint32_t dst, const float* src, int sz){
    asm volatile("cp.async.cg.shared.global [%0], [%1], 16, %2;"
                 :: "r"(dst), "l"(src), "r"(sz));
}
__device__ __forceinline__ void cp_commit(){ asm volatile("cp.async.commit_group;"); }
__device__ __forceinline__ void cp_wait1(){ asm volatile("cp.async.wait_group 1;"); }

// ---------------- TF32 TC GEMM (R10 core) + fused epilogues ----------------
// C[b][m][n] = sum_k A[m][k]*B(k,n) (+bias[m]) (+bias2[b][m]) (+relu)
//              (*1/(1e-9+colscale[b][n]))  [dsub: C = dsub - C]  (RNDC round)
// A: row-major [M,K] k-contig. B: !bT -> [K,N] n-contig ; bT -> [N,K] k-contig
// amax: atomicMax row-max into amax[b*M+m]. C may be null (skip store).
template<int CVTB, int RNDC>
__global__ __launch_bounds__(256, 2)
void mm_tc(const float* __restrict__ A, const float* __restrict__ B,
           const float* __restrict__ bias, const float* __restrict__ bias2,
           float* __restrict__ C,
           int M, int N, int K,
           long a_bat, long b_bat, long c_bat, int relu, int bT,
           const float* __restrict__ colscale, const float* __restrict__ dsub,
           unsigned int* __restrict__ amax)
{
    extern __shared__ float sm[];
    const float* Ab = A + (long)blockIdx.z * a_bat;
    const float* Bb = B + (long)blockIdx.z * b_bat;
    float*       Cb = C ? (C + (long)blockIdx.z * c_bat) : nullptr;
    const int bm = blockIdx.y * BM, bn = blockIdx.x * BN;
    const int tid = threadIdx.x;
    const int lane = tid & 31, wid = tid >> 5;
    const int wm = wid >> 2, wn = wid & 3;
    const int grp = lane >> 2, tig = lane & 3;
    const int ntiles = (K + BKT - 1) / BKT;
    const uint32_t sbase = (uint32_t)__cvta_generic_to_shared(sm);

    float acc[4][4][4];
#pragma unroll
    for (int i = 0; i < 4; i++)
#pragma unroll
        for (int j = 0; j < 4; j++)
#pragma unroll
            for (int r = 0; r < 4; r++) acc[i][j][r] = 0.f;

    auto prefetch = [&](int t){
        if (t >= ntiles) return;
        const int buf = t % 3;
        const uint32_t as0 = sbase + (uint32_t)(buf * STAGE_FLOATS) * 4u;
        const uint32_t bs0 = as0 + (uint32_t)(128 * ASTRIDE) * 4u;
        const int k0 = t * BKT;
#pragma unroll
        for (int i = 0; i < 4; i++) {
            int idx = tid + i*256;
            int mm = idx >> 3, kq = (idx & 7) << 2;
            long kg = (long)k0 + kq;
            long rem = ((long)K - kg) * 4;
            int sz = rem >= 16 ? 16 : (rem > 0 ? (int)rem : 0);
            const float* src = (sz > 0) ? (Ab + (long)(bm + mm)*K + kg) : Ab;
            cp16(as0 + (uint32_t)(mm*ASTRIDE + kq)*4u, src, sz);
        }
        if (!bT) {
#pragma unroll
            for (int i = 0; i < 4; i++) {
                int idx = tid + i*256;
                int kk = idx >> 5, nq = (idx & 31) << 2;
                long kg = (long)k0 + kk;
                int sz = (kg < K) ? 16 : 0;
                const float* src = (sz > 0) ? (Bb + kg*(long)N + (bn + nq)) : Bb;
                cp16(bs0 + (uint32_t)(kk*BSTRIDE + nq)*4u, src, sz);
            }
        } else {
#pragma unroll
            for (int i = 0; i < 4; i++) {
                int idx = tid + i*256;
                int nn = idx >> 3, kq = (idx & 7) << 2;
                long kg = (long)k0 + kq;
                long rem = ((long)K - kg) * 4;
                int sz = rem >= 16 ? 16 : (rem > 0 ? (int)rem : 0);
                const float* src = (sz > 0) ? (Bb + (long)(bn + nn)*K + kg) : Bb;
                cp16(bs0 + (uint32_t)(nn*ASTRIDE + kq)*4u, src, sz);
            }
        }
    };

    prefetch(0); cp_commit();
    prefetch(1); cp_commit();

    for (int t = 0; t < ntiles; t++) {
        cp_wait1();
        __syncthreads();
        const float* As = sm + (t % 3) * STAGE_FLOATS;
        const float* Bs = As + 128 * ASTRIDE;
        const uint32_t* Asu = (const uint32_t*)As;
        const uint32_t* Bsu = (const uint32_t*)Bs;

#pragma unroll
        for (int ks = 0; ks < 4; ks++) {
            const int kb = ks * 8;
            uint32_t af[4][4], bf[4][2];
#pragma unroll
            for (int i = 0; i < 4; i++) {
                int m0 = wm*64 + i*16 + grp;
                const uint32_t* r0 = Asu + m0*ASTRIDE;
                const uint32_t* r1 = r0 + 8*ASTRIDE;
                af[i][0] = r0[kb+tig];
                af[i][1] = r1[kb+tig];
                af[i][2] = r0[kb+tig+4];
                af[i][3] = r1[kb+tig+4];
            }
            if (!bT) {
#pragma unroll
                for (int j = 0; j < 4; j++) {
                    int n0 = wn*32 + j*8 + grp;
                    uint32_t v0 = Bsu[(kb+tig)*BSTRIDE + n0];
                    uint32_t v1 = Bsu[(kb+tig+4)*BSTRIDE + n0];
                    bf[j][0] = CVTB ? f2tf(__uint_as_float(v0)) : v0;
                    bf[j][1] = CVTB ? f2tf(__uint_as_float(v1)) : v1;
                }
            } else {
#pragma unroll
                for (int j = 0; j < 4; j++) {
                    int n0 = wn*32 + j*8 + grp;
                    uint32_t v0 = Bsu[n0*ASTRIDE + kb+tig];
                    uint32_t v1 = Bsu[n0*ASTRIDE + kb+tig+4];
                    bf[j][0] = CVTB ? f2tf(__uint_as_float(v0)) : v0;
                    bf[j][1] = CVTB ? f2tf(__uint_as_float(v1)) : v1;
                }
            }
#pragma unroll
            for (int i = 0; i < 4; i++)
#pragma unroll
                for (int j = 0; j < 4; j++)
                    mma_tf32(acc[i][j], af[i][0], af[i][1], af[i][2], af[i][3],
                             bf[j][0], bf[j][1]);
        }
        prefetch(t + 2); cp_commit();
    }

    const float* csb = colscale ? (colscale + (long)blockIdx.z * N) : nullptr;
    const float* db  = dsub ? (dsub + (long)blockIdx.z * c_bat) : nullptr;

#pragma unroll
    for (int i = 0; i < 4; i++) {
        int mg = bm + wm*64 + i*16 + grp;
        float bi0 = bias ? bias[mg]   : 0.f;
        float bi1 = bias ? bias[mg+8] : 0.f;
        if (bias2) {
            bi0 += bias2[(long)blockIdx.z*M + mg];
            bi1 += bias2[(long)blockIdx.z*M + mg+8];
        }
        float rm0 = -3.402823466e38f, rm1 = -3.402823466e38f;
#pragma unroll
        for (int j = 0; j < 4; j++) {
            int ng = bn + wn*32 + j*8 + tig*2;
            float2 v0, v1;
            v0.x = acc[i][j][0] + bi0; v0.y = acc[i][j][1] + bi0;
            v1.x = acc[i][j][2] + bi1; v1.y = acc[i][j][3] + bi1;
            if (relu) {
                v0.x = fmaxf(v0.x, 0.f); v0.y = fmaxf(v0.y, 0.f);
                v1.x = fmaxf(v1.x, 0.f); v1.y = fmaxf(v1.y, 0.f);
            }
            if (csb) {
                float2 c2 = *(const float2*)(csb + ng);
                float s0 = 1.f / (1e-9f + c2.x), s1 = 1.f / (1e-9f + c2.y);
                v0.x *= s0; v0.y *= s1; v1.x *= s0; v1.y *= s1;
            }
            if (db) {
                float2 d0 = *(const float2*)&db[(long)mg*N + ng];
                float2 d1 = *(const float2*)&db[(long)(mg+8)*N + ng];
                v0.x = d0.x - v0.x; v0.y = d0.y - v0.y;
                v1.x = d1.x - v1.x; v1.y = d1.y - v1.y;
            }
            if (RNDC) {
                v0.x = rnd(v0.x); v0.y = rnd(v0.y);
                v1.x = rnd(v1.x); v1.y = rnd(v1.y);
            }
            if (amax) {
                rm0 = fmaxf(rm0, fmaxf(v0.x, v0.y));
                rm1 = fmaxf(rm1, fmaxf(v1.x, v1.y));
            }
            if (Cb) {
                *(float2*)&Cb[(long)mg*N + ng]     = v0;
                *(float2*)&Cb[(long)(mg+8)*N + ng] = v1;
            }
        }
        if (amax) {
            rm0 = fmaxf(rm0, __shfl_xor_sync(0xffffffffu, rm0, 1));
            rm0 = fmaxf(rm0, __shfl_xor_sync(0xffffffffu, rm0, 2));
            rm1 = fmaxf(rm1, __shfl_xor_sync(0xffffffffu, rm1, 1));
            rm1 = fmaxf(rm1, __shfl_xor_sync(0xffffffffu, rm1, 2));
            if (tig == 0) {
                unsigned int* ab = amax + (long)blockIdx.z * M;
                atomicMax(&ab[mg],   fenc(rm0));
                atomicMax(&ab[mg+8], fenc(rm1));
            }
        }
    }
}

// ---------------- merged prologue: initmax + posenc + w1pad ----------------
__global__ void prep_k(const float* __restrict__ x, float* __restrict__ h24,
                       const float* __restrict__ w1, float* __restrict__ w1p,
                       unsigned int* __restrict__ gmu, unsigned int* __restrict__ omaxu)
{
    int idx = blockIdx.x*256 + threadIdx.x;
    if (idx < BATCH*1024) {
        omaxu[idx] = 0u;
        if (idx < BATCH*256) gmu[idx] = 0u;
    }
    if (idx < 128*24) {
        int m = idx / 24, k = idx % 24;
        w1p[idx] = (k < 21) ? rnd(w1[m*21 + k]) : 0.f;
    }
    if (idx >= BATCH*3*NPTS) return;
    int n = idx % NPTS; int r = idx / NPTS;
    int dim = r % 3, b = r / 3;
    float t = x[((long)b*3 + dim)*NPTS + n];
    float* o = h24 + (long)b*24*NPTS + n;
    o[(long)(dim     )*NPTS] = rnd(t);
    o[(long)(3  + dim)*NPTS] = rnd(sinf(t));
    o[(long)(6  + dim)*NPTS] = rnd(cosf(t));
    o[(long)(9  + dim)*NPTS] = rnd(sinf(2.f*t));
    o[(long)(12 + dim)*NPTS] = rnd(cosf(2.f*t));
    o[(long)(15 + dim)*NPTS] = rnd(sinf(4.f*t));
    o[(long)(18 + dim)*NPTS] = rnd(cosf(4.f*t));
    o[(long)(21 + dim)*NPTS] = 0.f;
}

// ---------------- one-shot tf32 rounding of weights (w3: packed lower half) ----------------
#define N4_W2  8192
#define N4_W3L 32768
#define N4_W4  131072
#define N4_WQK 16384
#define N4_WV  65536
#define N4_WT  65536
#define N4_TOT (N4_W2 + N4_W3L + N4_W4 + N4_WQK + N4_WV + N4_WT)
__global__ void rndall_k(const float4* w2, const float4* w3, const float4* w4,
                         const float4* wqk, const float4* wv, const float4* wt,
                         float4* w2r, float4* w3l, float4* w4r,
                         float4* wqkr, float4* wvr, float4* wtr)
{
    int i = blockIdx.x*256 + threadIdx.x;
    if (i >= N4_TOT) return;
    float4 v; float4* d;
    if (i < N4_W2) { v = w2[i]; d = w2r + i; }
    else if (i < N4_W2 + N4_W3L) {
        int j = i - N4_W2;
        int m = j >> 6, kq = j & 63;
        v = w3[m*128 + kq];
        d = w3l + j;
    }
    else if (i < N4_W2 + N4_W3L + N4_W4) { int j = i - (N4_W2+N4_W3L); v = w4[j]; d = w4r + j; }
    else if (i < N4_W2 + N4_W3L + N4_W4 + N4_WQK) { int j = i - (N4_W2+N4_W3L+N4_W4); v = wqk[j]; d = wqkr + j; }
    else if (i < N4_W2 + N4_W3L + N4_W4 + N4_WQK + N4_WV) { int j = i - (N4_W2+N4_W3L+N4_W4+N4_WQK); v = wv[j]; d = wvr + j; }
    else { int j = i - (N4_W2+N4_W3L+N4_W4+N4_WQK+N4_WV); v = wt[j]; d = wtr + j; }
    v.x = rnd(v.x); v.y = rnd(v.y); v.z = rnd(v.z); v.w = rnd(v.w);
    *d = v;
}

// ---------------- vb[b][m] = sum_c rnd(w3[m][256+c]) * gm[b][c] ----------------
__global__ void vbias_k(const float* __restrict__ w3, const unsigned int* __restrict__ gmu,
                        float* __restrict__ vb)
{
    int warp = threadIdx.x >> 5, lane = threadIdx.x & 31;
    int m = blockIdx.x*8 + warp;
    int b = blockIdx.y;
    const float* wrow = w3 + (long)m*512 + 256;
    float s = 0.f;
#pragma unroll
    for (int j = 0; j < 8; j++) {
        int c = lane + 32*j;
        s += rnd(wrow[c]) * fdec(gmu[b*256 + c]);
    }
#pragma unroll
    for (int o = 16; o > 0; o >>= 1) s += __shfl_xor_sync(0xffffffffu, s, o);
    if (lane == 0) vb[b*512 + m] = s;
}

// ---------------- transpose qk [128,N] -> qkT [N,128] ----------------
__global__ void tqk_k(const float* __restrict__ qk, float* __restrict__ qkT)
{
    __shared__ float s[32][33];
    int b = blockIdx.z;
    int n0 = blockIdx.x*32, c0 = blockIdx.y*32;
    const float* src = qk + (long)b*128*NPTS;
    float*       dst = qkT + (long)b*NPTS*128;
    int x = threadIdx.x, y = threadIdx.y;
#pragma unroll
    for (int i = 0; i < 4; i++)
        s[y+8*i][x] = src[(long)(c0+y+8*i)*NPTS + n0+x];
    __syncthreads();
#pragma unroll
    for (int i = 0; i < 4; i++)
        dst[(long)(n0+y+8*i)*128 + c0+x] = s[x][y+8*i];
}

// ---------------- warp-per-row softmax + fused per-block colsum partials ----------------
__global__ __launch_bounds__(256)
void softmax_k(float* __restrict__ attn, float* __restrict__ cspart)
{
    __shared__ float4 csm4[NPTS/4];       // 8 KB
    int warp = threadIdx.x >> 5, lane = threadIdx.x & 31;
    size_t row = (size_t)blockIdx.x*8 + warp;
    float4* p = (float4*)(attn + row * (size_t)NPTS);
    float4 v[16];
#pragma unroll
    for (int i = 0; i < 16; i++) v[i] = p[lane + 32*i];
    float m = -3.402823466e38f;
#pragma unroll
    for (int i = 0; i < 16; i++)
        m = fmaxf(m, fmaxf(fmaxf(v[i].x, v[i].y), fmaxf(v[i].z, v[i].w)));
#pragma unroll
    for (int o = 16; o > 0; o >>= 1) m = fmaxf(m, __shfl_xor_sync(0xffffffffu, m, o));
    float s = 0.f;
#pragma unroll
    for (int i = 0; i < 16; i++) {
        v[i].x = __expf(v[i].x - m); v[i].y = __expf(v[i].y - m);
        v[i].z = __expf(v[i].z - m); v[i].w = __expf(v[i].w - m);
        s += v[i].x + v[i].y + v[i].z + v[i].w;
    }
#pragma unroll
    for (int o = 16; o > 0; o >>= 1) s += __shfl_xor_sync(0xffffffffu, s, o);
    float inv = 1.f / s;
#pragma unroll
    for (int i = 0; i < 16; i++) {
        v[i].x = rnd(v[i].x * inv); v[i].y = rnd(v[i].y * inv);
        v[i].z = rnd(v[i].z * inv); v[i].w = rnd(v[i].w * inv);
        p[lane + 32*i] = v[i];
    }
    // deterministic per-block column partials (warps add in fixed order)
#pragma unroll
    for (int w = 0; w < 8; w++) {
        if (warp == w) {
#pragma unroll
            for (int i = 0; i < 16; i++) {
                if (w == 0) csm4[lane + 32*i] = v[i];
                else {
                    float4 a = csm4[lane + 32*i];
                    a.x += v[i].x; a.y += v[i].y; a.z += v[i].z; a.w += v[i].w;
                    csm4[lane + 32*i] = a;
                }
            }
        }
        __syncthreads();
    }
    float4* cp = (float4*)(cspart + (size_t)blockIdx.x * NPTS);
#pragma unroll
    for (int i = 0; i < 2; i++)
        cp[threadIdx.x + 256*i] = csm4[threadIdx.x + 256*i];
}

// ---------------- reduce 256 per-block partials -> cs[b][k] ----------------
__global__ void csred_k(const float* __restrict__ cspart, float* __restrict__ cs)
{
    int i = blockIdx.x*256 + threadIdx.x;
    if (i >= BATCH*NPTS) return;
    int b = i / NPTS, k = i % NPTS;
    const float* p = cspart + (size_t)b*256*NPTS + k;
    float s = 0.f;
#pragma unroll 8
    for (int j = 0; j < 256; j++) s += p[(size_t)j*NPTS];
    cs[i] = s;
}

// ---------------- BN batch stats per channel (float4 loads) ----------------
__global__ void bnstats_k(const float* __restrict__ d)
{
    int c = blockIdx.x;
    int t = threadIdx.x;
    double s = 0.0, s2 = 0.0;
    for (int i4 = t; i4 < BATCH*NPTS/4; i4 += 256) {
        int b = i4 / (NPTS/4), n4 = i4 % (NPTS/4);
        float4 v = ((const float4*)(d + ((long)b*512 + c)*NPTS))[n4];
        s  += (double)v.x + (double)v.y + (double)v.z + (double)v.w;
        s2 += (double)v.x*v.x + (double)v.y*v.y + (double)v.z*v.z + (double)v.w*v.w;
    }
    __shared__ double sh[256], sh2[256];
    sh[t] = s; sh2[t] = s2; __syncthreads();
    for (int o = 128; o > 0; o >>= 1) {
        if (t < o) { sh[t] += sh[t+o]; sh2[t] += sh2[t+o]; }
        __syncthreads();
    }
    if (t == 0) {
        double mu  = sh[0]  / (double)(BATCH*NPTS);
        double var = sh2[0] / (double)(BATCH*NPTS) - mu*mu;
        g_mu[c] = (float)mu;
        g_rs[c] = (float)(1.0 / sqrt(var + 1e-5));
    }
}

// ---------------- h2 = rnd(h + relu(bn(d))) (float4) ----------------
__global__ void bnapply_k(const float* __restrict__ h, const float* __restrict__ d,
                          const float* __restrict__ gamma, const float* __restrict__ beta,
                          float* __restrict__ h2)
{
    long i = (long)blockIdx.x*256 + threadIdx.x;
    if (i >= (long)BATCH*512*NPTS/4) return;
    int c = (int)((i / (NPTS/4)) % 512);
    float ga = gamma[c], mu = g_mu[c], rs = g_rs[c], be = beta[c];
    float4 dv = ((const float4*)d)[i];
    float4 hv = ((const float4*)h)[i];
    float4 r;
    r.x = rnd(hv.x + fmaxf(ga*(dv.x - mu)*rs + be, 0.f));
    r.y = rnd(hv.y + fmaxf(ga*(dv.y - mu)*rs + be, 0.f));
    r.z = rnd(hv.z + fmaxf(ga*(dv.z - mu)*rs + be, 0.f));
    r.w = rnd(hv.w + fmaxf(ga*(dv.w - mu)*rs + be, 0.f));
    ((float4*)h2)[i] = r;
}

// ---------------- decode ordered-uint maxes into fp32 output ----------------
__global__ void decout_k(const unsigned int* __restrict__ omaxu, float* __restrict__ out)
{
    int i = blockIdx.x*256 + threadIdx.x;
    if (i >= BATCH*1024) return;
    out[i] = fdec(omaxu[i]);
}

// ---------------- launch ----------------
extern "C" void kernel_launch(void* const* d_in, const int* in_sizes, int n_in,
                              void* d_out, int out_size)
{
    const float* x    = (const float*)d_in[0];
    const float* w1   = (const float*)d_in[1];
    const float* b1   = (const float*)d_in[2];
    const float* w2   = (const float*)d_in[3];
    const float* b2   = (const float*)d_in[4];
    const float* w3   = (const float*)d_in[5];
    const float* b3   = (const float*)d_in[6];
    const float* w4   = (const float*)d_in[7];
    const float* b4   = (const float*)d_in[8];
    const float* wqk  = (const float*)d_in[9];
    const float* wv   = (const float*)d_in[10];
    const float* bv   = (const float*)d_in[11];
    const float* wt   = (const float*)d_in[12];
    const float* bt   = (const float*)d_in[13];
    const float* gamma= (const float*)d_in[14];
    const float* beta = (const float*)d_in[15];
    float* out = (float*)d_out;

    static bool attr_set = false;
    if (!attr_set) {
        cudaFuncSetAttribute(mm_tc<0,0>, cudaFuncAttributeMaxDynamicSharedMemorySize, SMEM_BYTES);
        cudaFuncSetAttribute(mm_tc<0,1>, cudaFuncAttributeMaxDynamicSharedMemorySize, SMEM_BYTES);
        cudaFuncSetAttribute(mm_tc<1,1>, cudaFuncAttributeMaxDynamicSharedMemorySize, SMEM_BYTES);
        attr_set = true;
    }

    float *h24,*w1p,*w2r,*w3l,*w4r,*wqkr,*wvr,*wtr,*vb;
    float *h128,*hcat,*h,*qk,*qkT,*xv,*attn,*cs,*cspart,*hmxr,*dd,*h2;
    unsigned int *gmu,*omaxu;
    cudaGetSymbolAddress((void**)&h24,  g_h24);
    cudaGetSymbolAddress((void**)&w1p,  g_w1p);
    cudaGetSymbolAddress((void**)&w2r,  g_w2r);
    cudaGetSymbolAddress((void**)&w3l,  g_w3l);
    cudaGetSymbolAddress((void**)&w4r,  g_w4r);
    cudaGetSymbolAddress((void**)&wqkr, g_wqkr);
    cudaGetSymbolAddress((void**)&wvr,  g_wvr);
    cudaGetSymbolAddress((void**)&wtr,  g_wtr);
    cudaGetSymbolAddress((void**)&vb,   g_vb);
    cudaGetSymbolAddress((void**)&h128, g_h128);
    cudaGetSymbolAddress((void**)&gmu,  g_gmu);
    cudaGetSymbolAddress((void**)&omaxu,g_omaxu);
    cudaGetSymbolAddress((void**)&hcat, g_hcat);
    cudaGetSymbolAddress((void**)&h,    g_h);
    cudaGetSymbolAddress((void**)&qk,   g_qk);
    cudaGetSymbolAddress((void**)&qkT,  g_qkT);
    cudaGetSymbolAddress((void**)&xv,   g_xv);
    cudaGetSymbolAddress((void**)&attn, g_attn);
    cudaGetSymbolAddress((void**)&cs,   g_cs);
    cudaGetSymbolAddress((void**)&cspart, g_cspart);
    cudaGetSymbolAddress((void**)&hmxr, g_hmxr);
    cudaGetSymbolAddress((void**)&dd,   g_dd);
    cudaGetSymbolAddress((void**)&h2,   g_h2);

    const long EW = (long)BATCH*512*NPTS;

    // merged prologue: initmax + posenc + w1pad
    prep_k<<<(BATCH*3*NPTS + 255)/256, 256>>>(x, h24, w1, w1p, gmu, omaxu);
    rndall_k<<<(N4_TOT + 255)/256, 256>>>(
        (const float4*)w2, (const float4*)w3, (const float4*)w4,
        (const float4*)wqk, (const float4*)wv, (const float4*)wt,
        (float4*)w2r, (float4*)w3l, (float4*)w4r,
        (float4*)wqkr, (float4*)wvr, (float4*)wtr);

    // conv1 (24->128) + relu, rounded out
    mm_tc<0,1><<<dim3(16,1,BATCH),256,SMEM_BYTES>>>(w1p, h24, b1, nullptr, h128,
        128, NPTS, 24, 0, (long)24*NPTS, (long)128*NPTS, 1, 0, nullptr, nullptr, nullptr);
    // conv2 (128->256), rounded, hcat lower half + fused global max
    mm_tc<0,1><<<dim3(16,2,BATCH),256,SMEM_BYTES>>>(w2r, h128, b2, nullptr, hcat,
        256, NPTS, 128, 0, (long)128*NPTS, (long)512*NPTS, 0, 0, nullptr, nullptr, gmu);
    vbias_k<<<dim3(64, BATCH), 256>>>(w3, gmu, vb);
    // conv3 lower half (K=256) + vb + relu -> h
    mm_tc<0,0><<<dim3(16,4,BATCH),256,SMEM_BYTES>>>(w3l, hcat, b3, vb, h,
        512, NPTS, 256, 0, (long)512*NPTS, (long)512*NPTS, 1, 0, nullptr, nullptr, nullptr);
    // q/k projection (tied weights), B=h needs cvt, rounded out
    mm_tc<1,1><<<dim3(16,1,BATCH),256,SMEM_BYTES>>>(wqkr, h, nullptr, nullptr, qk,
        128, NPTS, 512, 0, (long)512*NPTS, (long)128*NPTS, 0, 0, nullptr, nullptr, nullptr);
    tqk_k<<<dim3(NPTS/32, 4, BATCH), dim3(32,8)>>>(qk, qkT);
    // energy = qkT @ qk (R10-proven path)
    mm_tc<0,0><<<dim3(16,16,BATCH),256,SMEM_BYTES>>>(qkT, qk, nullptr, nullptr, attn,
        NPTS, NPTS, 128, (long)NPTS*128, (long)128*NPTS, (long)NPTS*NPTS, 0, 0,
        nullptr, nullptr, nullptr);
    // softmax + fused per-block column partials
    softmax_k<<<BATCH*NPTS/8, 256>>>(attn, cspart);
    csred_k<<<(BATCH*NPTS + 255)/256, 256>>>(cspart, cs);
    // v projection with fused colsum scale, rounded
    mm_tc<1,1><<<dim3(16,4,BATCH),256,SMEM_BYTES>>>(wvr, h, bv, nullptr, xv,
        512, NPTS, 512, 0, (long)512*NPTS, (long)512*NPTS, 0, 0, cs, nullptr, nullptr);
    // hmxr = rnd(h - xv_scaled @ attn^T)
    mm_tc<0,1><<<dim3(16,4,BATCH),256,SMEM_BYTES>>>(xv, attn, nullptr, nullptr, hmxr,
        512, NPTS, NPTS, (long)512*NPTS, (long)NPTS*NPTS, (long)512*NPTS, 0, 1,
        nullptr, h, nullptr);
    // d = wt @ (h - x_r) + bt
    mm_tc<0,0><<<dim3(16,4,BATCH),256,SMEM_BYTES>>>(wtr, hmxr, bt, nullptr, dd,
        512, NPTS, 512, 0, (long)512*NPTS, (long)512*NPTS, 0, 0, nullptr, nullptr, nullptr);
    bnstats_k<<<512, 256>>>(dd);
    bnapply_k<<<(int)((EW/4 + 255)/256), 256>>>(h, dd, gamma, beta, h2);
    // conv4 (512->1024) fused with final max-over-N
    mm_tc<0,0><<<dim3(16,8,BATCH),256,SMEM_BYTES>>>(w4r, h2, b4, nullptr, nullptr,
        1024, NPTS, 512, 0, (long)512*NPTS, 0, 0, 0, nullptr, nullptr, omaxu);
    decout_k<<<(BATCH*1024 + 255)/256, 256>>>(omaxu, out);
}

// round 15
// speedup vs baseline: 1.1733x; 1.0345x over previous
#include <cuda_runtime.h>
#include <math.h>
#include <stdint.h>

#define BATCH 16
#define NPTS  2048
#define BM 128
#define BN 128
#define BKT 32
#define ASTRIDE 36      // (36*grp+tig) mod 32 = 4*grp+tig -> all 32 banks distinct
#define BSTRIDE 136
#define STAGE_FLOATS (128*ASTRIDE + 128*ASTRIDE)   // 9216
#define SMEM_BYTES (3 * STAGE_FLOATS * 4)          // 110592

// ---------------- scratch (device globals) ----------------
__device__ float g_h24 [(size_t)BATCH*24*NPTS];
__device__ float g_w1p [128*24];
__device__ float g_w2r [256*128];
__device__ float g_w3l [512*256];
__device__ float g_w4r [1024*512];
__device__ float g_wqkr[128*512];
__device__ float g_wvr [512*512];
__device__ float g_wtr [512*512];
__device__ float g_vb  [BATCH*512];
__device__ float g_h128[(size_t)BATCH*128*NPTS];
__device__ unsigned int g_gmu  [BATCH*256];
__device__ unsigned int g_omaxu[BATCH*1024];
__device__ float g_hcat[(size_t)BATCH*512*NPTS];
__device__ float g_h   [(size_t)BATCH*512*NPTS];
__device__ float g_qk  [(size_t)BATCH*128*NPTS];
__device__ float g_qkT [(size_t)BATCH*NPTS*128];
__device__ float g_xv  [(size_t)BATCH*512*NPTS];
__device__ float g_attn[(size_t)BATCH*NPTS*NPTS];   // 256 MB
__device__ float g_cs  [BATCH*NPTS];
__device__ float g_cspart[(size_t)BATCH*256*NPTS];
__device__ float g_hmxr[(size_t)BATCH*512*NPTS];
__device__ float g_dd  [(size_t)BATCH*512*NPTS];
__device__ float g_mu  [512];
__device__ float g_rs  [512];
__device__ float g_h2  [(size_t)BATCH*512*NPTS];

// ---------------- helpers ----------------
__device__ __forceinline__ uint32_t f2tf(float f){
    uint32_t u;
    asm("cvt.rna.tf32.f32 %0, %1;" : "=r"(u) : "f"(f));
    return u;
}
__device__ __forceinline__ float rnd(float f){ return __uint_as_float(f2tf(f)); }

__device__ __forceinline__ unsigned int fenc(float f){
    unsigned int u = __float_as_uint(f);
    return (u >> 31) ? ~u : (u | 0x80000000u);
}
__device__ __forceinline__ float fdec(unsigned int u){
    return __uint_as_float((u >> 31) ? (u ^ 0x80000000u) : ~u);
}

__device__ __forceinline__ void mma_tf32(float c[4], uint32_t a0, uint32_t a1,
                                         uint32_t a2, uint32_t a3,
                                         uint32_t b0, uint32_t b1){
    asm volatile(
        "mma.sync.aligned.m16n8k8.row.col.f32.tf32.tf32.f32 "
        "{%0,%1,%2,%3}, {%4,%5,%6,%7}, {%8,%9}, {%0,%1,%2,%3};"
        : "+f"(c[0]), "+f"(c[1]), "+f"(c[2]), "+f"(c[3])
        : "r"(a0), "r"(a1), "r"(a2), "r"(a3), "r"(b0), "r"(b1));
}

__device__ __forceinline__ void ldsm4(uint32_t& r0, uint32_t& r1, uint32_t& r2,
                                      uint32_t& r3, uint32_t addr){
    asm volatile("ldmatrix.sync.aligned.m8n8.x4.shared.b16 {%0,%1,%2,%3}, [%4];"
                 : "=r"(r0), "=r"(r1), "=r"(r2), "=r"(r3) : "r"(addr));
}

__device__ __forceinline__ void cp16(uint32_t dst, const float* src, int sz){
    asm volatile("cp.async.cg.shared.global [%0], [%1], 16, %2;"
                 :: "r"(dst), "l"(src), "r"(sz));
}
__device__ __forceinline__ void cp_commit(){ asm volatile("cp.async.commit_group;"); }
__device__ __forceinline__ void cp_wait1(){ asm volatile("cp.async.wait_group 1;"); }

// ---------------- TF32 TC GEMM (R10 core) + ldmatrix fragment loads ----------------
// Same smem layout as R10; only the load instructions changed.
template<int CVTB, int RNDC>
__global__ __launch_bounds__(256, 2)
void mm_tc(const float* __restrict__ A, const float* __restrict__ B,
           const float* __restrict__ bias, const float* __restrict__ bias2,
           float* __restrict__ C,
           int M, int N, int K,
           long a_bat, long b_bat, long c_bat, int relu, int bT,
           const float* __restrict__ colscale, const float* __restrict__ dsub,
           unsigned int* __restrict__ amax)
{
    extern __shared__ float sm[];
    const float* Ab = A + (long)blockIdx.z * a_bat;
    const float* Bb = B + (long)blockIdx.z * b_bat;
    float*       Cb = C ? (C + (long)blockIdx.z * c_bat) : nullptr;
    const int bm = blockIdx.y * BM, bn = blockIdx.x * BN;
    const int tid = threadIdx.x;
    const int lane = tid & 31, wid = tid >> 5;
    const int wm = wid >> 2, wn = wid & 3;
    const int grp = lane >> 2, tig = lane & 3;
    const int ntiles = (K + BKT - 1) / BKT;
    const uint32_t sbase = (uint32_t)__cvta_generic_to_shared(sm);

    // ldmatrix lane-invariant offsets (element units)
    // A x4: tiles {a0,a1,a2,a3} = rows(W..W+7 / W+8..W+15) x wordcols(kb / kb+4)
    const int a_row_off = (lane & 7) + 8*((lane >> 3) & 1);
    const int a_col_off = 4*(lane >> 4);
    // bT-B x4: tiles {b[j][0], b[j][1], b[j+1][0], b[j+1][1]}
    const int b_row_off = (lane & 7) + 8*(lane >> 4);
    const int b_col_off = 4*((lane >> 3) & 1);
    // per-i A lane offsets (elements, modulo kb which is added per ks)
    int a_loff[4];
#pragma unroll
    for (int i = 0; i < 4; i++)
        a_loff[i] = (wm*64 + i*16 + a_row_off)*ASTRIDE + a_col_off;
    // per-j (j=0,2) bT-B lane offsets
    int b_loff[2];
#pragma unroll
    for (int j = 0; j < 2; j++)
        b_loff[j] = (wn*32 + j*16 + b_row_off)*ASTRIDE + b_col_off;

    float acc[4][4][4];
#pragma unroll
    for (int i = 0; i < 4; i++)
#pragma unroll
        for (int j = 0; j < 4; j++)
#pragma unroll
            for (int r = 0; r < 4; r++) acc[i][j][r] = 0.f;

    auto prefetch = [&](int t){
        if (t >= ntiles) return;
        const int buf = t % 3;
        const uint32_t as0 = sbase + (uint32_t)(buf * STAGE_FLOATS) * 4u;
        const uint32_t bs0 = as0 + (uint32_t)(128 * ASTRIDE) * 4u;
        const int k0 = t * BKT;
#pragma unroll
        for (int i = 0; i < 4; i++) {
            int idx = tid + i*256;
            int mm = idx >> 3, kq = (idx & 7) << 2;
            long kg = (long)k0 + kq;
            long rem = ((long)K - kg) * 4;
            int sz = rem >= 16 ? 16 : (rem > 0 ? (int)rem : 0);
            const float* src = (sz > 0) ? (Ab + (long)(bm + mm)*K + kg) : Ab;
            cp16(as0 + (uint32_t)(mm*ASTRIDE + kq)*4u, src, sz);
        }
        if (!bT) {
#pragma unroll
            for (int i = 0; i < 4; i++) {
                int idx = tid + i*256;
                int kk = idx >> 5, nq = (idx & 31) << 2;
                long kg = (long)k0 + kk;
                int sz = (kg < K) ? 16 : 0;
                const float* src = (sz > 0) ? (Bb + kg*(long)N + (bn + nq)) : Bb;
                cp16(bs0 + (uint32_t)(kk*BSTRIDE + nq)*4u, src, sz);
            }
        } else {
#pragma unroll
            for (int i = 0; i < 4; i++) {
                int idx = tid + i*256;
                int nn = idx >> 3, kq = (idx & 7) << 2;
                long kg = (long)k0 + kq;
                long rem = ((long)K - kg) * 4;
                int sz = rem >= 16 ? 16 : (rem > 0 ? (int)rem : 0);
                const float* src = (sz > 0) ? (Bb + (long)(bn + nn)*K + kg) : Bb;
                cp16(bs0 + (uint32_t)(nn*ASTRIDE + kq)*4u, src, sz);
            }
        }
    };

    prefetch(0); cp_commit();
    prefetch(1); cp_commit();

    for (int t = 0; t < ntiles; t++) {
        cp_wait1();
        __syncthreads();
        const uint32_t as_addr = sbase + (uint32_t)((t % 3) * STAGE_FLOATS) * 4u;
        const uint32_t bs_addr = as_addr + (uint32_t)(128 * ASTRIDE) * 4u;
        const float* Bs = sm + (t % 3) * STAGE_FLOATS + 128 * ASTRIDE;
        const uint32_t* Bsu = (const uint32_t*)Bs;

#pragma unroll
        for (int ks = 0; ks < 4; ks++) {
            const int kb = ks * 8;
            uint32_t af[4][4], bf[4][2];
#pragma unroll
            for (int i = 0; i < 4; i++)
                ldsm4(af[i][0], af[i][1], af[i][2], af[i][3],
                      as_addr + (uint32_t)(a_loff[i] + kb)*4u);
            if (!bT) {
#pragma unroll
                for (int j = 0; j < 4; j++) {
                    int n0 = wn*32 + j*8 + grp;
                    uint32_t v0 = Bsu[(kb+tig)*BSTRIDE + n0];
                    uint32_t v1 = Bsu[(kb+tig+4)*BSTRIDE + n0];
                    bf[j][0] = CVTB ? f2tf(__uint_as_float(v0)) : v0;
                    bf[j][1] = CVTB ? f2tf(__uint_as_float(v1)) : v1;
                }
            } else {
#pragma unroll
                for (int j = 0; j < 2; j++) {
                    ldsm4(bf[2*j][0], bf[2*j][1], bf[2*j+1][0], bf[2*j+1][1],
                          bs_addr + (uint32_t)(b_loff[j] + kb)*4u);
                    if (CVTB) {
                        bf[2*j][0] = f2tf(__uint_as_float(bf[2*j][0]));
                        bf[2*j][1] = f2tf(__uint_as_float(bf[2*j][1]));
                        bf[2*j+1][0] = f2tf(__uint_as_float(bf[2*j+1][0]));
                        bf[2*j+1][1] = f2tf(__uint_as_float(bf[2*j+1][1]));
                    }
                }
            }
#pragma unroll
            for (int i = 0; i < 4; i++)
#pragma unroll
                for (int j = 0; j < 4; j++)
                    mma_tf32(acc[i][j], af[i][0], af[i][1], af[i][2], af[i][3],
                             bf[j][0], bf[j][1]);
        }
        prefetch(t + 2); cp_commit();
    }

    const float* csb = colscale ? (colscale + (long)blockIdx.z * N) : nullptr;
    const float* db  = dsub ? (dsub + (long)blockIdx.z * c_bat) : nullptr;

#pragma unroll
    for (int i = 0; i < 4; i++) {
        int mg = bm + wm*64 + i*16 + grp;
        float bi0 = bias ? bias[mg]   : 0.f;
        float bi1 = bias ? bias[mg+8] : 0.f;
        if (bias2) {
            bi0 += bias2[(long)blockIdx.z*M + mg];
            bi1 += bias2[(long)blockIdx.z*M + mg+8];
        }
        float rm0 = -3.402823466e38f, rm1 = -3.402823466e38f;
#pragma unroll
        for (int j = 0; j < 4; j++) {
            int ng = bn + wn*32 + j*8 + tig*2;
            float2 v0, v1;
            v0.x = acc[i][j][0] + bi0; v0.y = acc[i][j][1] + bi0;
            v1.x = acc[i][j][2] + bi1; v1.y = acc[i][j][3] + bi1;
            if (relu) {
                v0.x = fmaxf(v0.x, 0.f); v0.y = fmaxf(v0.y, 0.f);
                v1.x = fmaxf(v1.x, 0.f); v1.y = fmaxf(v1.y, 0.f);
            }
            if (csb) {
                float2 c2 = *(const float2*)(csb + ng);
                float s0 = 1.f / (1e-9f + c2.x), s1 = 1.f / (1e-9f + c2.y);
                v0.x *= s0; v0.y *= s1; v1.x *= s0; v1.y *= s1;
            }
            if (db) {
                float2 d0 = *(const float2*)&db[(long)mg*N + ng];
                float2 d1 = *(const float2*)&db[(long)(mg+8)*N + ng];
                v0.x = d0.x - v0.x; v0.y = d0.y - v0.y;
                v1.x = d1.x - v1.x; v1.y = d1.y - v1.y;
            }
            if (RNDC) {
                v0.x = rnd(v0.x); v0.y = rnd(v0.y);
                v1.x = rnd(v1.x); v1.y = rnd(v1.y);
            }
            if (amax) {
                rm0 = fmaxf(rm0, fmaxf(v0.x, v0.y));
                rm1 = fmaxf(rm1, fmaxf(v1.x, v1.y));
            }
            if (Cb) {
                *(float2*)&Cb[(long)mg*N + ng]     = v0;
                *(float2*)&Cb[(long)(mg+8)*N + ng] = v1;
            }
        }
        if (amax) {
            rm0 = fmaxf(rm0, __shfl_xor_sync(0xffffffffu, rm0, 1));
            rm0 = fmaxf(rm0, __shfl_xor_sync(0xffffffffu, rm0, 2));
            rm1 = fmaxf(rm1, __shfl_xor_sync(0xffffffffu, rm1, 1));
            rm1 = fmaxf(rm1, __shfl_xor_sync(0xffffffffu, rm1, 2));
            if (tig == 0) {
                unsigned int* ab = amax + (long)blockIdx.z * M;
                atomicMax(&ab[mg],   fenc(rm0));
                atomicMax(&ab[mg+8], fenc(rm1));
            }
        }
    }
}

// ---------------- merged prologue: initmax + posenc + w1pad ----------------
__global__ void prep_k(const float* __restrict__ x, float* __restrict__ h24,
                       const float* __restrict__ w1, float* __restrict__ w1p,
                       unsigned int* __restrict__ gmu, unsigned int* __restrict__ omaxu)
{
    int idx = blockIdx.x*256 + threadIdx.x;
    if (idx < BATCH*1024) {
        omaxu[idx] = 0u;
        if (idx < BATCH*256) gmu[idx] = 0u;
    }
    if (idx < 128*24) {
        int m = idx / 24, k = idx % 24;
        w1p[idx] = (k < 21) ? rnd(w1[m*21 + k]) : 0.f;
    }
    if (idx >= BATCH*3*NPTS) return;
    int n = idx % NPTS; int r = idx / NPTS;
    int dim = r % 3, b = r / 3;
    float t = x[((long)b*3 + dim)*NPTS + n];
    float* o = h24 + (long)b*24*NPTS + n;
    o[(long)(dim     )*NPTS] = rnd(t);
    o[(long)(3  + dim)*NPTS] = rnd(sinf(t));
    o[(long)(6  + dim)*NPTS] = rnd(cosf(t));
    o[(long)(9  + dim)*NPTS] = rnd(sinf(2.f*t));
    o[(long)(12 + dim)*NPTS] = rnd(cosf(2.f*t));
    o[(long)(15 + dim)*NPTS] = rnd(sinf(4.f*t));
    o[(long)(18 + dim)*NPTS] = rnd(cosf(4.f*t));
    o[(long)(21 + dim)*NPTS] = 0.f;
}

// ---------------- one-shot tf32 rounding of weights ----------------
#define N4_W2  8192
#define N4_W3L 32768
#define N4_W4  131072
#define N4_WQK 16384
#define N4_WV  65536
#define N4_WT  65536
#define N4_TOT (N4_W2 + N4_W3L + N4_W4 + N4_WQK + N4_WV + N4_WT)
__global__ void rndall_k(const float4* w2, const float4* w3, const float4* w4,
                         const float4* wqk, const float4* wv, const float4* wt,
                         float4* w2r, float4* w3l, float4* w4r,
                         float4* wqkr, float4* wvr, float4* wtr)
{
    int i = blockIdx.x*256 + threadIdx.x;
    if (i >= N4_TOT) return;
    float4 v; float4* d;
    if (i < N4_W2) { v = w2[i]; d = w2r + i; }
    else if (i < N4_W2 + N4_W3L) {
        int j = i - N4_W2;
        int m = j >> 6, kq = j & 63;
        v = w3[m*128 + kq];
        d = w3l + j;
    }
    else if (i < N4_W2 + N4_W3L + N4_W4) { int j = i - (N4_W2+N4_W3L); v = w4[j]; d = w4r + j; }
    else if (i < N4_W2 + N4_W3L + N4_W4 + N4_WQK) { int j = i - (N4_W2+N4_W3L+N4_W4); v = wqk[j]; d = wqkr + j; }
    else if (i < N4_W2 + N4_W3L + N4_W4 + N4_WQK + N4_WV) { int j = i - (N4_W2+N4_W3L+N4_W4+N4_WQK); v = wv[j]; d = wvr + j; }
    else { int j = i - (N4_W2+N4_W3L+N4_W4+N4_WQK+N4_WV); v = wt[j]; d = wtr + j; }
    v.x = rnd(v.x); v.y = rnd(v.y); v.z = rnd(v.z); v.w = rnd(v.w);
    *d = v;
}

// ---------------- vb[b][m] = sum_c rnd(w3[m][256+c]) * gm[b][c] ----------------
__global__ void vbias_k(const float* __restrict__ w3, const unsigned int* __restrict__ gmu,
                        float* __restrict__ vb)
{
    int warp = threadIdx.x >> 5, lane = threadIdx.x & 31;
    int m = blockIdx.x*8 + warp;
    int b = blockIdx.y;
    const float* wrow = w3 + (long)m*512 + 256;
    float s = 0.f;
#pragma unroll
    for (int j = 0; j < 8; j++) {
        int c = lane + 32*j;
        s += rnd(wrow[c]) * fdec(gmu[b*256 + c]);
    }
#pragma unroll
    for (int o = 16; o > 0; o >>= 1) s += __shfl_xor_sync(0xffffffffu, s, o);
    if (lane == 0) vb[b*512 + m] = s;
}

// ---------------- transpose qk [128,N] -> qkT [N,128] ----------------
__global__ void tqk_k(const float* __restrict__ qk, float* __restrict__ qkT)
{
    __shared__ float s[32][33];
    int b = blockIdx.z;
    int n0 = blockIdx.x*32, c0 = blockIdx.y*32;
    const float* src = qk + (long)b*128*NPTS;
    float*       dst = qkT + (long)b*NPTS*128;
    int x = threadIdx.x, y = threadIdx.y;
#pragma unroll
    for (int i = 0; i < 4; i++)
        s[y+8*i][x] = src[(long)(c0+y+8*i)*NPTS + n0+x];
    __syncthreads();
#pragma unroll
    for (int i = 0; i < 4; i++)
        dst[(long)(n0+y+8*i)*128 + c0+x] = s[x][y+8*i];
}

// ---------------- warp-per-row softmax + fused per-block colsum partials ----------------
__global__ __launch_bounds__(256)
void softmax_k(float* __restrict__ attn, float* __restrict__ cspart)
{
    __shared__ float4 csm4[NPTS/4];
    int warp = threadIdx.x >> 5, lane = threadIdx.x & 31;
    size_t row = (size_t)blockIdx.x*8 + warp;
    float4* p = (float4*)(attn + row * (size_t)NPTS);
    float4 v[16];
#pragma unroll
    for (int i = 0; i < 16; i++) v[i] = p[lane + 32*i];
    float m = -3.402823466e38f;
#pragma unroll
    for (int i = 0; i < 16; i++)
        m = fmaxf(m, fmaxf(fmaxf(v[i].x, v[i].y), fmaxf(v[i].z, v[i].w)));
#pragma unroll
    for (int o = 16; o > 0; o >>= 1) m = fmaxf(m, __shfl_xor_sync(0xffffffffu, m, o));
    float s = 0.f;
#pragma unroll
    for (int i = 0; i < 16; i++) {
        v[i].x = __expf(v[i].x - m); v[i].y = __expf(v[i].y - m);
        v[i].z = __expf(v[i].z - m); v[i].w = __expf(v[i].w - m);
        s += v[i].x + v[i].y + v[i].z + v[i].w;
    }
#pragma unroll
    for (int o = 16; o > 0; o >>= 1) s += __shfl_xor_sync(0xffffffffu, s, o);
    float inv = 1.f / s;
#pragma unroll
    for (int i = 0; i < 16; i++) {
        v[i].x = rnd(v[i].x * inv); v[i].y = rnd(v[i].y * inv);
        v[i].z = rnd(v[i].z * inv); v[i].w = rnd(v[i].w * inv);
        p[lane + 32*i] = v[i];
    }
#pragma unroll
    for (int w = 0; w < 8; w++) {
        if (warp == w) {
#pragma unroll
            for (int i = 0; i < 16; i++) {
                if (w == 0) csm4[lane + 32*i] = v[i];
                else {
                    float4 a = csm4[lane + 32*i];
                    a.x += v[i].x; a.y += v[i].y; a.z += v[i].z; a.w += v[i].w;
                    csm4[lane + 32*i] = a;
                }
            }
        }
        __syncthreads();
    }
    float4* cp = (float4*)(cspart + (size_t)blockIdx.x * NPTS);
#pragma unroll
    for (int i = 0; i < 2; i++)
        cp[threadIdx.x + 256*i] = csm4[threadIdx.x + 256*i];
}

// ---------------- reduce 256 per-block partials -> cs[b][k] ----------------
__global__ void csred_k(const float* __restrict__ cspart, float* __restrict__ cs)
{
    int i = blockIdx.x*256 + threadIdx.x;
    if (i >= BATCH*NPTS) return;
    int b = i / NPTS, k = i % NPTS;
    const float* p = cspart + (size_t)b*256*NPTS + k;
    float s = 0.f;
#pragma unroll 8
    for (int j = 0; j < 256; j++) s += p[(size_t)j*NPTS];
    cs[i] = s;
}

// ---------------- BN batch stats per channel ----------------
__global__ void bnstats_k(const float* __restrict__ d)
{
    int c = blockIdx.x;
    int t = threadIdx.x;
    double s = 0.0, s2 = 0.0;
    for (int i4 = t; i4 < BATCH*NPTS/4; i4 += 256) {
        int b = i4 / (NPTS/4), n4 = i4 % (NPTS/4);
        float4 v = ((const float4*)(d + ((long)b*512 + c)*NPTS))[n4];
        s  += (double)v.x + (double)v.y + (double)v.z + (double)v.w;
        s2 += (double)v.x*v.x + (double)v.y*v.y + (double)v.z*v.z + (double)v.w*v.w;
    }
    __shared__ double sh[256], sh2[256];
    sh[t] = s; sh2[t] = s2; __syncthreads();
    for (int o = 128; o > 0; o >>= 1) {
        if (t < o) { sh[t] += sh[t+o]; sh2[t] += sh2[t+o]; }
        __syncthreads();
    }
    if (t == 0) {
        double mu  = sh[0]  / (double)(BATCH*NPTS);
        double var = sh2[0] / (double)(BATCH*NPTS) - mu*mu;
        g_mu[c] = (float)mu;
        g_rs[c] = (float)(1.0 / sqrt(var + 1e-5));
    }
}

// ---------------- h2 = rnd(h + relu(bn(d))) ----------------
__global__ void bnapply_k(const float* __restrict__ h, const float* __restrict__ d,
                          const float* __restrict__ gamma, const float* __restrict__ beta,
                          float* __restrict__ h2)
{
    long i = (long)blockIdx.x*256 + threadIdx.x;
    if (i >= (long)BATCH*512*NPTS/4) return;
    int c = (int)((i / (NPTS/4)) % 512);
    float ga = gamma[c], mu = g_mu[c], rs = g_rs[c], be = beta[c];
    float4 dv = ((const float4*)d)[i];
    float4 hv = ((const float4*)h)[i];
    float4 r;
    r.x = rnd(hv.x + fmaxf(ga*(dv.x - mu)*rs + be, 0.f));
    r.y = rnd(hv.y + fmaxf(ga*(dv.y - mu)*rs + be, 0.f));
    r.z = rnd(hv.z + fmaxf(ga*(dv.z - mu)*rs + be, 0.f));
    r.w = rnd(hv.w + fmaxf(ga*(dv.w - mu)*rs + be, 0.f));
    ((float4*)h2)[i] = r;
}

// ---------------- decode ordered-uint maxes into fp32 output ----------------
__global__ void decout_k(const unsigned int* __restrict__ omaxu, float* __restrict__ out)
{
    int i = blockIdx.x*256 + threadIdx.x;
    if (i >= BATCH*1024) return;
    out[i] = fdec(omaxu[i]);
}

// ---------------- launch ----------------
extern "C" void kernel_launch(void* const* d_in, const int* in_sizes, int n_in,
                              void* d_out, int out_size)
{
    const float* x    = (const float*)d_in[0];
    const float* w1   = (const float*)d_in[1];
    const float* b1   = (const float*)d_in[2];
    const float* w2   = (const float*)d_in[3];
    const float* b2   = (const float*)d_in[4];
    const float* w3   = (const float*)d_in[5];
    const float* b3   = (const float*)d_in[6];
    const float* w4   = (const float*)d_in[7];
    const float* b4   = (const float*)d_in[8];
    const float* wqk  = (const float*)d_in[9];
    const float* wv   = (const float*)d_in[10];
    const float* bv   = (const float*)d_in[11];
    const float* wt   = (const float*)d_in[12];
    const float* bt   = (const float*)d_in[13];
    const float* gamma= (const float*)d_in[14];
    const float* beta = (const float*)d_in[15];
    float* out = (float*)d_out;

    static bool attr_set = false;
    if (!attr_set) {
        cudaFuncSetAttribute(mm_tc<0,0>, cudaFuncAttributeMaxDynamicSharedMemorySize, SMEM_BYTES);
        cudaFuncSetAttribute(mm_tc<0,1>, cudaFuncAttributeMaxDynamicSharedMemorySize, SMEM_BYTES);
        cudaFuncSetAttribute(mm_tc<1,1>, cudaFuncAttributeMaxDynamicSharedMemorySize, SMEM_BYTES);
        attr_set = true;
    }

    float *h24,*w1p,*w2r,*w3l,*w4r,*wqkr,*wvr,*wtr,*vb;
    float *h128,*hcat,*h,*qk,*qkT,*xv,*attn,*cs,*cspart,*hmxr,*dd,*h2;
    unsigned int *gmu,*omaxu;
    cudaGetSymbolAddress((void**)&h24,  g_h24);
    cudaGetSymbolAddress((void**)&w1p,  g_w1p);
    cudaGetSymbolAddress((void**)&w2r,  g_w2r);
    cudaGetSymbolAddress((void**)&w3l,  g_w3l);
    cudaGetSymbolAddress((void**)&w4r,  g_w4r);
    cudaGetSymbolAddress((void**)&wqkr, g_wqkr);
    cudaGetSymbolAddress((void**)&wvr,  g_wvr);
    cudaGetSymbolAddress((void**)&wtr,  g_wtr);
    cudaGetSymbolAddress((void**)&vb,   g_vb);
    cudaGetSymbolAddress((void**)&h128, g_h128);
    cudaGetSymbolAddress((void**)&gmu,  g_gmu);
    cudaGetSymbolAddress((void**)&omaxu,g_omaxu);
    cudaGetSymbolAddress((void**)&hcat, g_hcat);
    cudaGetSymbolAddress((void**)&h,    g_h);
    cudaGetSymbolAddress((void**)&qk,   g_qk);
    cudaGetSymbolAddress((void**)&qkT,  g_qkT);
    cudaGetSymbolAddress((void**)&xv,   g_xv);
    cudaGetSymbolAddress((void**)&attn, g_attn);
    cudaGetSymbolAddress((void**)&cs,   g_cs);
    cudaGetSymbolAddress((void**)&cspart, g_cspart);
    cudaGetSymbolAddress((void**)&hmxr, g_hmxr);
    cudaGetSymbolAddress((void**)&dd,   g_dd);
    cudaGetSymbolAddress((void**)&h2,   g_h2);

    const long EW = (long)BATCH*512*NPTS;

    prep_k<<<(BATCH*3*NPTS + 255)/256, 256>>>(x, h24, w1, w1p, gmu, omaxu);
    rndall_k<<<(N4_TOT + 255)/256, 256>>>(
        (const float4*)w2, (const float4*)w3, (const float4*)w4,
        (const float4*)wqk, (const float4*)wv, (const float4*)wt,
        (float4*)w2r, (float4*)w3l, (float4*)w4r,
        (float4*)wqkr, (float4*)wvr, (float4*)wtr);

    // conv1 (24->128) + relu, rounded out
    mm_tc<0,1><<<dim3(16,1,BATCH),256,SMEM_BYTES>>>(w1p, h24, b1, nullptr, h128,
        128, NPTS, 24, 0, (long)24*NPTS, (long)128*NPTS, 1, 0, nullptr, nullptr, nullptr);
    // conv2 (128->256), rounded, hcat lower half + fused global max
    mm_tc<0,1><<<dim3(16,2,BATCH),256,SMEM_BYTES>>>(w2r, h128, b2, nullptr, hcat,
        256, NPTS, 128, 0, (long)128*NPTS, (long)512*NPTS, 0, 0, nullptr, nullptr, gmu);
    vbias_k<<<dim3(64, BATCH), 256>>>(w3, gmu, vb);
    // conv3 lower half (K=256) + vb + relu -> h
    mm_tc<0,0><<<dim3(16,4,BATCH),256,SMEM_BYTES>>>(w3l, hcat, b3, vb, h,
        512, NPTS, 256, 0, (long)512*NPTS, (long)512*NPTS, 1, 0, nullptr, nullptr, nullptr);
    // q/k projection (tied weights), B=h needs cvt, rounded out
    mm_tc<1,1><<<dim3(16,1,BATCH),256,SMEM_BYTES>>>(wqkr, h, nullptr, nullptr, qk,
        128, NPTS, 512, 0, (long)512*NPTS, (long)128*NPTS, 0, 0, nullptr, nullptr, nullptr);
    tqk_k<<<dim3(NPTS/32, 4, BATCH), dim3(32,8)>>>(qk, qkT);
    // energy = qkT @ qk
    mm_tc<0,0><<<dim3(16,16,BATCH),256,SMEM_BYTES>>>(qkT, qk, nullptr, nullptr, attn,
        NPTS, NPTS, 128, (long)NPTS*128, (long)128*NPTS, (long)NPTS*NPTS, 0, 0,
        nullptr, nullptr, nullptr);
    // softmax + fused per-block column partials
    softmax_k<<<BATCH*NPTS/8, 256>>>(attn, cspart);
    csred_k<<<(BATCH*NPTS + 255)/256, 256>>>(cspart, cs);
    // v projection with fused colsum scale, rounded
    mm_tc<1,1><<<dim3(16,4,BATCH),256,SMEM_BYTES>>>(wvr, h, bv, nullptr, xv,
        512, NPTS, 512, 0, (long)512*NPTS, (long)512*NPTS, 0, 0, cs, nullptr, nullptr);
    // hmxr = rnd(h - xv_scaled @ attn^T)  [bT: ldmatrix B path]
    mm_tc<0,1><<<dim3(16,4,BATCH),256,SMEM_BYTES>>>(xv, attn, nullptr, nullptr, hmxr,
        512, NPTS, NPTS, (long)512*NPTS, (long)NPTS*NPTS, (long)512*NPTS, 0, 1,
        nullptr, h, nullptr);
    // d = wt @ (h - x_r) + bt
    mm_tc<0,0><<<dim3(16,4,BATCH),256,SMEM_BYTES>>>(wtr, hmxr, bt, nullptr, dd,
        512, NPTS, 512, 0, (long)512*NPTS, (long)512*NPTS, 0, 0, nullptr, nullptr, nullptr);
    bnstats_k<<<512, 256>>>(dd);
    bnapply_k<<<(int)((EW/4 + 255)/256), 256>>>(h, dd, gamma, beta, h2);
    // conv4 (512->1024) fused with final max-over-N
    mm_tc<0,0><<<dim3(16,8,BATCH),256,SMEM_BYTES>>>(w4r, h2, b4, nullptr, nullptr,
        1024, NPTS, 512, 0, (long)512*NPTS, 0, 0, 0, nullptr, nullptr, omaxu);
    decout_k<<<(BATCH*1024 + 255)/256, 256>>>(omaxu, out);
}